// round 11
// baseline (speedup 1.0000x reference)
#include <cuda_runtime.h>
#include <cuda_bf16.h>
#include <math_constants.h>
#include <cstdint>

#define Bn 8
#define Cn 64
#define Hn 128
#define Wn 128

// ---------------------------------------------------------------------------
// Global scratch (no allocation allowed)
// ---------------------------------------------------------------------------
__device__ uint32_t g_qh[Bn*Hn*Wn*32], g_ql[Bn*Hn*Wn*32];
__device__ uint32_t g_kh[Bn*Hn*Wn*32], g_kl[Bn*Hn*Wn*32];
__device__ uint32_t g_vh[Bn*Hn*Wn*32], g_vl[Bn*Hn*Wn*32];
__device__ uint32_t g_xh[Bn*Hn*32*Wn], g_xl[Bn*Hn*32*Wn];
__device__ float g_oH[Bn*Hn*Wn*Cn];         // [b][w][h][c]  (unnormalized)
__device__ float g_oW[Bn*Hn*Wn*Cn];         // [b][h][w][c]  (unnormalized)
__device__ float2 g_msH[Bn*Hn*Wn];          // per-pixel (m, sumexp) of eH half
__device__ float2 g_msW[Bn*Hn*Wn];
__device__ float2 g_al[Bn*Hn*Wn];           // per-pixel (alphaH, alphaW)
__device__ __align__(16) char g_wb16[3*3*3*2*8192];

// ---------------------------------------------------------------------------
// helpers
// ---------------------------------------------------------------------------
__device__ __forceinline__ uint32_t smem_u32(const void* p) {
    uint32_t a;
    asm("{ .reg .u64 t; cvta.to.shared.u64 t, %1; cvt.u32.u64 %0, t; }"
        : "=r"(a) : "l"(p));
    return a;
}
__device__ __forceinline__ void ldsm4(uint32_t* r, uint32_t addr) {
    asm volatile("ldmatrix.sync.aligned.m8n8.x4.shared.b16 {%0,%1,%2,%3}, [%4];"
        : "=r"(r[0]), "=r"(r[1]), "=r"(r[2]), "=r"(r[3]) : "r"(addr));
}
__device__ __forceinline__ void mma16816(float (&d)[4], const uint32_t (&a)[4],
                                         uint32_t b0, uint32_t b1) {
    asm volatile("mma.sync.aligned.m16n8k16.row.col.f32.bf16.bf16.f32 "
        "{%0,%1,%2,%3}, {%4,%5,%6,%7}, {%8,%9}, {%0,%1,%2,%3};"
        : "+f"(d[0]), "+f"(d[1]), "+f"(d[2]), "+f"(d[3])
        : "r"(a[0]), "r"(a[1]), "r"(a[2]), "r"(a[3]), "r"(b0), "r"(b1));
}
__device__ __forceinline__ void split_pack(float a, float b,
                                           uint32_t& hp, uint32_t& lp) {
    __nv_bfloat16 ha = __float2bfloat16(a);
    __nv_bfloat16 hb = __float2bfloat16(b);
    __nv_bfloat16 la = __float2bfloat16(a - __bfloat162float(ha));
    __nv_bfloat16 lb = __float2bfloat16(b - __bfloat162float(hb));
    hp = ((uint32_t)__bfloat16_as_ushort(hb) << 16) | __bfloat16_as_ushort(ha);
    lp = ((uint32_t)__bfloat16_as_ushort(lb) << 16) | __bfloat16_as_ushort(la);
}

// ---------------------------------------------------------------------------
// Weight prep (unchanged)
// ---------------------------------------------------------------------------
__global__ void prep_w_k(const float* __restrict__ Wq,
                         const float* __restrict__ Wk,
                         const float* __restrict__ Wv)
{
    int i = blockIdx.x*blockDim.x + threadIdx.x;
    if (i >= 3*3*3*64*64) return;
    int ci = i & 63; int t = i >> 6;
    int co = t & 63; t >>= 6;
    int kx = t % 3;  t /= 3;
    int ky = t % 3;  t /= 3;
    int sel = t;
    const float* Ws = (sel == 0) ? Wq : ((sel == 1) ? Wk : Wv);
    float v = Ws[((co*Cn + ci)*3 + ky)*3 + kx];
    __nv_bfloat16 hi = __float2bfloat16(v);
    __nv_bfloat16 lo = __float2bfloat16(v - __bfloat162float(hi));
    size_t tbase = (size_t)(((sel*3 + ky)*3 + kx)*2)*8192;
    uint32_t off = (uint32_t)co*128 + (((uint32_t)ci*2) ^ (((uint32_t)co & 7) << 4));
    *(__nv_bfloat16*)(g_wb16 + tbase + off)        = hi;
    *(__nv_bfloat16*)(g_wb16 + tbase + 8192 + off) = lo;
}

// ---------------------------------------------------------------------------
// x pre-split: NCHW fp32 -> [b][h][cp][w] packed bf16 hi/lo
// ---------------------------------------------------------------------------
__global__ __launch_bounds__(256) void prep_x_k(const float* __restrict__ x)
{
    int id = blockIdx.x*256 + threadIdx.x;
    int w = id & 127, cp = (id >> 7) & 31, h = (id >> 12) & 127, b = id >> 19;
    float v0 = x[(((size_t)(b*64 + cp*2    ))*128 + h)*128 + w];
    float v1 = x[(((size_t)(b*64 + cp*2 + 1))*128 + h)*128 + w];
    uint32_t hp, lp;
    split_pack(v0, v1, hp, lp);
    g_xh[id] = hp;
    g_xl[id] = lp;
}

// ---------------------------------------------------------------------------
// Fused 3x3 conv via mma.sync — software pipelined (unchanged R9)
// ---------------------------------------------------------------------------
#define CONV_SMEM (73728 + 133120 + 128)

__global__ __launch_bounds__(256) void conv_mma_k(const float* __restrict__ bq,
                                                  const float* __restrict__ bk,
                                                  const float* __restrict__ bv)
{
    extern __shared__ char sm[];
    char* SW = sm;                     // 18 x 4096
    char* SA = sm + 73728;             // 8 x 16640  [slot*2 + split]
    float* sbias = (float*)(sm + 73728 + 133120);
    const int tid = threadIdx.x, lane = tid & 31, wid = tid >> 5;
    const int b = blockIdx.y;
    const int sel = blockIdx.z >> 1, co0 = (blockIdx.z & 1) * 32;
    const int h0 = blockIdx.x * 8;
    const float* bias = (sel == 0) ? bq : ((sel == 1) ? bk : bv);
    uint32_t* gh = (sel == 0) ? g_qh : ((sel == 1) ? g_kh : g_vh);
    uint32_t* gl = (sel == 0) ? g_ql : ((sel == 1) ? g_kl : g_vl);

    {
        const char* gw = g_wb16 + (size_t)sel*9*2*8192 + (size_t)co0*128;
        for (int i = tid; i < 18*256; i += 256) {
            int t = i >> 8, seg = i & 255;
            *(uint4*)(SW + t*4096 + seg*16) =
                *(const uint4*)(gw + (size_t)t*8192 + seg*16);
        }
    }
    if (tid < 32) sbias[tid] = bias[co0 + tid];
    if (tid < 128) {
        int s8 = tid / 16, k = tid % 16;
        uint32_t off = s8*16640 + ((k < 8) ? 0u : 16512u) + (k & 7)*16;
        *(uint4*)(SA + off) = make_uint4(0,0,0,0);
    }

    for (int rr = -1; rr <= 1; rr++) {
        const int r = h0 + rr;
        const int s = (r + 4) & 3;
        char* hi = SA + (size_t)(s*2 + 0)*16640;
        char* lo = SA + (size_t)(s*2 + 1)*16640;
        const bool valid = ((unsigned)r < 128u);
        const uint32_t* xh = g_xh + (size_t)(b*Hn + (valid ? r : 0))*4096;
        const uint32_t* xl = g_xl + (size_t)(b*Hn + (valid ? r : 0))*4096;
#pragma unroll
        for (int j = 0; j < 16; j++) {
            int id = tid + j*256;
            int w = id & 127, cp = id >> 7;
            uint32_t hv = valid ? xh[id] : 0u;
            uint32_t lv = valid ? xl[id] : 0u;
            uint32_t row = (uint32_t)w + 1;
            uint32_t off = row*128 + (((uint32_t)cp*4) ^ ((row & 7) << 4));
            *(uint32_t*)(hi + off) = hv;
            *(uint32_t*)(lo + off) = lv;
        }
    }
    __syncthreads();

    const uint32_t SAb = smem_u32(SA);
    const uint32_t SWb = smem_u32(SW);
    const int m0 = wid * 16;
    const int aRowSel = lane & 15;
    const int aColSel = (lane & 16) ? 16 : 0;
    const int bRowSel = (lane & 7) + ((lane & 16) ? 8 : 0);
    const int bColSel = (lane & 8) ? 16 : 0;

    uint32_t aAO[3][4], bO[4];
#pragma unroll
    for (int kx = 0; kx < 3; kx++) {
        const int arow = m0 + kx + aRowSel;
        const uint32_t axor = ((uint32_t)arow & 7) << 4;
#pragma unroll
        for (int cc = 0; cc < 4; cc++)
            aAO[kx][cc] = (uint32_t)arow*128 + (((uint32_t)(cc*32 + aColSel)) ^ axor);
    }
    {
        const uint32_t bxor = ((uint32_t)bRowSel & 7) << 4;
#pragma unroll
        for (int cc = 0; cc < 4; cc++)
            bO[cc] = (uint32_t)bRowSel*128 + (((uint32_t)(cc*32 + bColSel)) ^ bxor);
    }

    for (int hh = 0; hh < 8; hh++) {
        const int h = h0 + hh;

        uint32_t ph[16], pl[16];
        const bool pf = (hh < 7);
        if (pf) {
            const int rn = h + 2;
            const bool valid = rn < 128;
            const uint32_t* xh = g_xh + (size_t)(b*Hn + (valid ? rn : 0))*4096;
            const uint32_t* xl = g_xl + (size_t)(b*Hn + (valid ? rn : 0))*4096;
#pragma unroll
            for (int j = 0; j < 16; j++) {
                int id = tid + j*256;
                ph[j] = valid ? xh[id] : 0u;
                pl[j] = valid ? xl[id] : 0u;
            }
        }

        float acc[4][4];
#pragma unroll
        for (int i = 0; i < 4; i++)
#pragma unroll
            for (int j = 0; j < 4; j++) acc[i][j] = 0.f;

#pragma unroll
        for (int ky = 0; ky < 3; ky++) {
            const int r = h + ky - 1;
            const int s = (r + 4) & 3;
            const uint32_t Ahi = SAb + (uint32_t)(s*2)*16640;
            const uint32_t Alo = Ahi + 16640;
#pragma unroll
            for (int kx = 0; kx < 3; kx++) {
                const uint32_t Wt = SWb + (uint32_t)((ky*3 + kx)*2)*4096;
#pragma unroll
                for (int cc = 0; cc < 4; cc++) {
                    uint32_t ah[4], al[4], bh[8], bl[8];
                    ldsm4(ah, Ahi + aAO[kx][cc]);
                    ldsm4(al, Alo + aAO[kx][cc]);
                    ldsm4(bh + 0, Wt + bO[cc]);
                    ldsm4(bh + 4, Wt + bO[cc] + 2048);
                    ldsm4(bl + 0, Wt + 4096 + bO[cc]);
                    ldsm4(bl + 4, Wt + 4096 + bO[cc] + 2048);
#pragma unroll
                    for (int nt = 0; nt < 4; nt++) {
                        mma16816(acc[nt], ah, bh[nt*2], bh[nt*2 + 1]);
                        mma16816(acc[nt], al, bh[nt*2], bh[nt*2 + 1]);
                        mma16816(acc[nt], ah, bl[nt*2], bl[nt*2 + 1]);
                    }
                }
            }
        }

        if (pf) {
            const int s = (h + 2 + 4) & 3;
            char* hi = SA + (size_t)(s*2 + 0)*16640;
            char* lo = SA + (size_t)(s*2 + 1)*16640;
#pragma unroll
            for (int j = 0; j < 16; j++) {
                int id = tid + j*256;
                int w = id & 127, cp = id >> 7;
                uint32_t row = (uint32_t)w + 1;
                uint32_t off = row*128 + (((uint32_t)cp*4) ^ ((row & 7) << 4));
                *(uint32_t*)(hi + off) = ph[j];
                *(uint32_t*)(lo + off) = pl[j];
            }
        }

        const int wr = m0 + (lane >> 2);
        const int cb = (lane & 3) * 2;
        const size_t rowBase = (size_t)(b*Hn + h)*Wn;
#pragma unroll
        for (int nt = 0; nt < 4; nt++) {
            const int c = co0 + nt*8 + cb;
            const float b0 = sbias[nt*8 + cb], b1 = sbias[nt*8 + cb + 1];
            uint32_t hp, lp;
            split_pack(acc[nt][0] + b0, acc[nt][1] + b1, hp, lp);
            gh[(rowBase + wr)*32 + (c >> 1)] = hp;
            gl[(rowBase + wr)*32 + (c >> 1)] = lp;
            split_pack(acc[nt][2] + b0, acc[nt][3] + b1, hp, lp);
            gh[(rowBase + wr + 8)*32 + (c >> 1)] = hp;
            gl[(rowBase + wr + 8)*32 + (c >> 1)] = lp;
        }
        __syncthreads();
    }
}

// ---------------------------------------------------------------------------
// FUSED attention (flash style). blockIdx.z: 0 = eH->out_H per (w,b),
// 1 = eW->out_W per (h,b).
// Logits 128x128 in registers -> local softmax (m,s) -> e=exp(l-m) ->
// C-fragments reused as A-fragments (hi/lo split) for P*V MMA.
// Writes unnormalized partials to g_oH/g_oW and (m,s) to g_msH/g_msW.
// ---------------------------------------------------------------------------
#define FUSED_SMEM (4*16384 + 4*8192)

__global__ __launch_bounds__(256) void fused_attn_k()
{
    extern __shared__ char sm[];
    char* QH = sm;            char* QL = sm + 16384;
    char* KH = sm + 32768;    char* KL = sm + 49152;
    char* VTH0 = sm + 65536;  char* VTH1 = sm + 73728;
    char* VTL0 = sm + 81920;  char* VTL1 = sm + 90112;
    const int tid = threadIdx.x, lane = tid & 31, wid = tid >> 5;
    const int p = blockIdx.x, b = blockIdx.y, mode = blockIdx.z;

    // q/k/v all read the same way: mode0 = column (w=p), mode1 = row (h=p)
    const size_t base32 = mode ? (size_t)((b*Hn + p)*Wn)*32
                               : (size_t)(b*Hn*Wn + p)*32;
    const int str32 = mode ? 32 : Wn*32;

    // Stage Q,K hi/lo
    for (int i = tid; i < 8192; i += 256) {
        int tsel = i >> 12, rem = i & 4095;
        int cp = rem & 31, r = rem >> 5;
        const uint32_t* sh = tsel ? g_kh : g_qh;
        const uint32_t* sl = tsel ? g_kl : g_ql;
        uint32_t hv = sh[base32 + (size_t)r*str32 + cp];
        uint32_t lv = sl[base32 + (size_t)r*str32 + cp];
        uint32_t off = (uint32_t)r*128 + (((uint32_t)cp*4) ^ (((uint32_t)r & 7) << 4));
        *(uint32_t*)((tsel ? KH : QH) + off) = hv;
        *(uint32_t*)((tsel ? KL : QL) + off) = lv;
    }
    // Stage V transposed: VT[c][g] hi/lo
    for (int i = tid; i < 4096; i += 256) {
        int cp = i & 31, g = i >> 5;
        uint32_t hv = g_vh[base32 + (size_t)g*str32 + cp];
        uint32_t lv = g_vl[base32 + (size_t)g*str32 + cp];
        int t = g >> 6, gin = g & 63;
        int c0 = cp*2, c1 = cp*2 + 1;
        uint32_t off0 = (uint32_t)c0*128 + (((uint32_t)gin*2) ^ (((uint32_t)c0 & 7) << 4));
        uint32_t off1 = (uint32_t)c1*128 + (((uint32_t)gin*2) ^ (((uint32_t)c1 & 7) << 4));
        *(uint16_t*)((t ? VTH1 : VTH0) + off0) = (uint16_t)(hv & 0xFFFF);
        *(uint16_t*)((t ? VTH1 : VTH0) + off1) = (uint16_t)(hv >> 16);
        *(uint16_t*)((t ? VTL1 : VTL0) + off0) = (uint16_t)(lv & 0xFFFF);
        *(uint16_t*)((t ? VTL1 : VTL0) + off1) = (uint16_t)(lv >> 16);
    }
    __syncthreads();

    const uint32_t QHb = smem_u32(QH), QLb = smem_u32(QL);
    const uint32_t KHb = smem_u32(KH), KLb = smem_u32(KL);
    const uint32_t VTH0b = smem_u32(VTH0), VTH1b = smem_u32(VTH1);
    const uint32_t VTL0b = smem_u32(VTL0), VTL1b = smem_u32(VTL1);
    const int m0 = wid * 16;
    const int aRowSel = lane & 15;
    const int aColSel = (lane & 16) ? 16 : 0;
    const int bRowSel = (lane & 7) + ((lane & 16) ? 8 : 0);
    const int bColSel = (lane & 8) ? 16 : 0;

    uint32_t aO[4], bO[4];
    {
        const int arow = m0 + aRowSel;
        const uint32_t axor = ((uint32_t)arow & 7) << 4;
        const uint32_t bxor = ((uint32_t)bRowSel & 7) << 4;
#pragma unroll
        for (int kc = 0; kc < 4; kc++) {
            aO[kc] = (uint32_t)arow*128 + (((uint32_t)(kc*32 + aColSel)) ^ axor);
            bO[kc] = (uint32_t)bRowSel*128 + (((uint32_t)(kc*32 + bColSel)) ^ bxor);
        }
    }

    // ---- Phase 1: logits 128x128 -> acc ----
    float acc[16][4];
#pragma unroll
    for (int i = 0; i < 16; i++)
#pragma unroll
        for (int j = 0; j < 4; j++) acc[i][j] = 0.f;

#pragma unroll
    for (int kc = 0; kc < 4; kc++) {
        uint32_t ah[4], al[4];
        ldsm4(ah, QHb + aO[kc]);
        ldsm4(al, QLb + aO[kc]);
#pragma unroll
        for (int half = 0; half < 2; half++) {
            uint32_t bh[16], bl[16];
#pragma unroll
            for (int t = 0; t < 4; t++) {
                const uint32_t boff = bO[kc] + (uint32_t)(half*4 + t)*2048;
                ldsm4(bh + 4*t, KHb + boff);
                ldsm4(bl + 4*t, KLb + boff);
            }
#pragma unroll
            for (int nt = 0; nt < 8; nt++) {
                const int a = half*8 + nt;
                mma16816(acc[a], ah, bh[nt*2], bh[nt*2 + 1]);
                mma16816(acc[a], al, bh[nt*2], bh[nt*2 + 1]);
                mma16816(acc[a], ah, bl[nt*2], bl[nt*2 + 1]);
            }
        }
    }

    // ---- Phase 2: mask + local softmax + e = exp(l - m) in place ----
    const int msBase = mode ? (b*Hn + p)*Wn : b*Hn*Wn + p;
    const int msStr  = mode ? 1 : Wn;
    float2* msOut = mode ? g_msW : g_msH;

#pragma unroll
    for (int half2 = 0; half2 < 2; half2++) {
        const int row = m0 + (lane >> 2) + half2*8;
        if (!mode) {
#pragma unroll
            for (int nt = 0; nt < 16; nt++) {
                const int g = nt*8 + (lane & 3)*2;
                if (row == g)     acc[nt][half2*2 + 0] = -CUDART_INF_F;
                if (row == g + 1) acc[nt][half2*2 + 1] = -CUDART_INF_F;
            }
        }
        float m = acc[0][half2*2];
#pragma unroll
        for (int nt = 0; nt < 16; nt++) {
            m = fmaxf(m, acc[nt][half2*2 + 0]);
            m = fmaxf(m, acc[nt][half2*2 + 1]);
        }
        m = fmaxf(m, __shfl_xor_sync(~0u, m, 1));
        m = fmaxf(m, __shfl_xor_sync(~0u, m, 2));
        float s = 0.f;
#pragma unroll
        for (int nt = 0; nt < 16; nt++) {
            float e0 = __expf(acc[nt][half2*2 + 0] - m);
            float e1 = __expf(acc[nt][half2*2 + 1] - m);
            acc[nt][half2*2 + 0] = e0;
            acc[nt][half2*2 + 1] = e1;
            s += e0 + e1;
        }
        s += __shfl_xor_sync(~0u, s, 1);
        s += __shfl_xor_sync(~0u, s, 2);
        if ((lane & 3) == 0) msOut[msBase + row*msStr] = make_float2(m, s);
    }

    // ---- Phase 3: out partial = P * V via fragment reuse ----
    float acc2[8][4];
#pragma unroll
    for (int i = 0; i < 8; i++)
#pragma unroll
        for (int j = 0; j < 4; j++) acc2[i][j] = 0.f;

#pragma unroll
    for (int kc = 0; kc < 8; kc++) {
        // A fragment from P (C-fragment reuse): k chunk g = 16kc..16kc+15
        uint32_t aH[4], aL[4];
        split_pack(acc[2*kc    ][0], acc[2*kc    ][1], aH[0], aL[0]);
        split_pack(acc[2*kc    ][2], acc[2*kc    ][3], aH[1], aL[1]);
        split_pack(acc[2*kc + 1][0], acc[2*kc + 1][1], aH[2], aL[2]);
        split_pack(acc[2*kc + 1][2], acc[2*kc + 1][3], aH[3], aL[3]);

        const uint32_t Bh = (kc < 4) ? VTH0b : VTH1b;
        const uint32_t Bl = (kc < 4) ? VTL0b : VTL1b;
        const int cc = kc & 3;
        uint32_t bh[16], bl[16];
#pragma unroll
        for (int t = 0; t < 4; t++) {
            const uint32_t boff = bO[cc] + (uint32_t)t*2048;
            ldsm4(bh + 4*t, Bh + boff);
            ldsm4(bl + 4*t, Bl + boff);
        }
#pragma unroll
        for (int nt = 0; nt < 8; nt++) {
            mma16816(acc2[nt], aH, bh[nt*2], bh[nt*2 + 1]);
            mma16816(acc2[nt], aL, bh[nt*2], bh[nt*2 + 1]);
            mma16816(acc2[nt], aH, bl[nt*2], bl[nt*2 + 1]);
        }
    }

    // ---- Epilogue: unnormalized partials ----
    float* oB = (mode ? g_oW : g_oH) + ((size_t)(b*Hn + p)*Wn)*Cn;
#pragma unroll
    for (int half2 = 0; half2 < 2; half2++) {
        const int row = m0 + (lane >> 2) + half2*8;
#pragma unroll
        for (int nt = 0; nt < 8; nt++) {
            const int c = nt*8 + (lane & 3)*2;
            *(float2*)&oB[(size_t)row*Cn + c] =
                make_float2(acc2[nt][half2*2 + 0], acc2[nt][half2*2 + 1]);
        }
    }
}

// ---------------------------------------------------------------------------
// Combine (m, s) halves -> per-pixel (alphaH, alphaW)
// ---------------------------------------------------------------------------
__global__ __launch_bounds__(256) void combine_ms_k()
{
    int i = blockIdx.x*256 + threadIdx.x;
    float2 a = g_msH[i], c = g_msW[i];
    float m = fmaxf(a.x, c.x);
    float eH = __expf(a.x - m), eW = __expf(c.x - m);
    float inv = 1.0f / (a.y*eH + c.y*eW);
    g_al[i] = make_float2(eH*inv, eW*inv);
}

// ---------------------------------------------------------------------------
// Final: out[b][c][h][w] = gamma*(oHp*aH + oWp*aW) + x
// ---------------------------------------------------------------------------
__global__ __launch_bounds__(256) void final_k(const float* __restrict__ x,
                                               const float* __restrict__ gamma,
                                               float* __restrict__ out)
{
    __shared__ float s[Cn][33];
    __shared__ float2 al[32];
    const int w0 = blockIdx.x*32, h = blockIdx.y, b = blockIdx.z;
    const float g = gamma[0];
    if (threadIdx.x < 32)
        al[threadIdx.x] = g_al[(b*Hn + h)*Wn + w0 + threadIdx.x];
    __syncthreads();
    for (int i = threadIdx.x; i < 32*Cn; i += 256) {
        int wl = i >> 6, c = i & 63;
        float a = g_oH[(((size_t)b*Wn + (w0+wl))*Hn + h)*Cn + c];
        float d = g_oW[(((size_t)b*Hn + h)*Wn + (w0+wl))*Cn + c];
        float2 av = al[wl];
        s[c][wl] = g*(a*av.x + d*av.y);
    }
    __syncthreads();
    for (int i = threadIdx.x; i < Cn*32; i += 256) {
        int c = i >> 5, wl = i & 31;
        size_t idx = (((size_t)b*Cn + c)*Hn + h)*Wn + w0 + wl;
        out[idx] = s[c][wl] + x[idx];
    }
}

// ---------------------------------------------------------------------------
extern "C" void kernel_launch(void* const* d_in, const int* in_sizes, int n_in,
                              void* d_out, int out_size)
{
    (void)in_sizes; (void)n_in; (void)out_size;
    const float* x     = (const float*)d_in[0];
    const float* Wq    = (const float*)d_in[1];
    const float* bq    = (const float*)d_in[2];
    const float* Wk    = (const float*)d_in[3];
    const float* bk    = (const float*)d_in[4];
    const float* Wv    = (const float*)d_in[5];
    const float* bv    = (const float*)d_in[6];
    const float* gamma = (const float*)d_in[7];
    float* out = (float*)d_out;

    static bool attr_set = false;
    if (!attr_set) {
        cudaFuncSetAttribute(conv_mma_k, cudaFuncAttributeMaxDynamicSharedMemorySize,
                             CONV_SMEM);
        cudaFuncSetAttribute(fused_attn_k, cudaFuncAttributeMaxDynamicSharedMemorySize,
                             FUSED_SMEM);
        attr_set = true;
    }

    prep_w_k<<<(3*3*3*64*64 + 255)/256, 256>>>(Wq, Wk, Wv);
    prep_x_k<<<(Bn*Hn*32*Wn)/256, 256>>>(x);

    dim3 grid_conv(16, Bn, 6);   // (htile, b, sel*2 + co-half)
    conv_mma_k<<<grid_conv, 256, CONV_SMEM>>>(bq, bk, bv);

    dim3 grid_at(128, Bn, 2);    // (p, b, mode)
    fused_attn_k<<<grid_at, 256, FUSED_SMEM>>>();

    combine_ms_k<<<(Bn*Hn*Wn)/256, 256>>>();

    dim3 grid_fin(Wn/32, Hn, Bn);
    final_k<<<grid_fin, 256>>>(x, gamma, out);
}

// round 12
// speedup vs baseline: 1.2266x; 1.2266x over previous
#include <cuda_runtime.h>
#include <cuda_bf16.h>
#include <math_constants.h>
#include <cstdint>

#define Bn 8
#define Cn 64
#define Hn 128
#define Wn 128

// ---------------------------------------------------------------------------
// Global scratch (no allocation allowed)
// ---------------------------------------------------------------------------
__device__ uint32_t g_qh[Bn*Hn*Wn*32], g_ql[Bn*Hn*Wn*32];
__device__ uint32_t g_kh[Bn*Hn*Wn*32], g_kl[Bn*Hn*Wn*32];
__device__ uint32_t g_vh[Bn*Hn*Wn*32], g_vl[Bn*Hn*Wn*32];
__device__ uint32_t g_xh[Bn*Hn*32*Wn], g_xl[Bn*Hn*32*Wn];
__device__ float g_oH[Bn*Hn*Wn*Cn];         // [b][w][h][c]  (unnormalized)
__device__ float g_oW[Bn*Hn*Wn*Cn];         // [b][h][w][c]  (unnormalized)
__device__ float2 g_msH[Bn*Hn*Wn];          // per-pixel (m, sumexp) of eH half
__device__ float2 g_msW[Bn*Hn*Wn];
__device__ float2 g_al[Bn*Hn*Wn];           // per-pixel (alphaH, alphaW)
__device__ __align__(16) char g_wb16[3*3*3*2*8192];

// ---------------------------------------------------------------------------
// helpers
// ---------------------------------------------------------------------------
__device__ __forceinline__ uint32_t smem_u32(const void* p) {
    uint32_t a;
    asm("{ .reg .u64 t; cvta.to.shared.u64 t, %1; cvt.u32.u64 %0, t; }"
        : "=r"(a) : "l"(p));
    return a;
}
__device__ __forceinline__ void ldsm4(uint32_t* r, uint32_t addr) {
    asm volatile("ldmatrix.sync.aligned.m8n8.x4.shared.b16 {%0,%1,%2,%3}, [%4];"
        : "=r"(r[0]), "=r"(r[1]), "=r"(r[2]), "=r"(r[3]) : "r"(addr));
}
__device__ __forceinline__ void mma16816(float (&d)[4], const uint32_t (&a)[4],
                                         uint32_t b0, uint32_t b1) {
    asm volatile("mma.sync.aligned.m16n8k16.row.col.f32.bf16.bf16.f32 "
        "{%0,%1,%2,%3}, {%4,%5,%6,%7}, {%8,%9}, {%0,%1,%2,%3};"
        : "+f"(d[0]), "+f"(d[1]), "+f"(d[2]), "+f"(d[3])
        : "r"(a[0]), "r"(a[1]), "r"(a[2]), "r"(a[3]), "r"(b0), "r"(b1));
}
__device__ __forceinline__ void split_pack(float a, float b,
                                           uint32_t& hp, uint32_t& lp) {
    __nv_bfloat16 ha = __float2bfloat16(a);
    __nv_bfloat16 hb = __float2bfloat16(b);
    __nv_bfloat16 la = __float2bfloat16(a - __bfloat162float(ha));
    __nv_bfloat16 lb = __float2bfloat16(b - __bfloat162float(hb));
    hp = ((uint32_t)__bfloat16_as_ushort(hb) << 16) | __bfloat16_as_ushort(ha);
    lp = ((uint32_t)__bfloat16_as_ushort(lb) << 16) | __bfloat16_as_ushort(la);
}

// ---------------------------------------------------------------------------
// Weight prep (unchanged)
// ---------------------------------------------------------------------------
__global__ void prep_w_k(const float* __restrict__ Wq,
                         const float* __restrict__ Wk,
                         const float* __restrict__ Wv)
{
    int i = blockIdx.x*blockDim.x + threadIdx.x;
    if (i >= 3*3*3*64*64) return;
    int ci = i & 63; int t = i >> 6;
    int co = t & 63; t >>= 6;
    int kx = t % 3;  t /= 3;
    int ky = t % 3;  t /= 3;
    int sel = t;
    const float* Ws = (sel == 0) ? Wq : ((sel == 1) ? Wk : Wv);
    float v = Ws[((co*Cn + ci)*3 + ky)*3 + kx];
    __nv_bfloat16 hi = __float2bfloat16(v);
    __nv_bfloat16 lo = __float2bfloat16(v - __bfloat162float(hi));
    size_t tbase = (size_t)(((sel*3 + ky)*3 + kx)*2)*8192;
    uint32_t off = (uint32_t)co*128 + (((uint32_t)ci*2) ^ (((uint32_t)co & 7) << 4));
    *(__nv_bfloat16*)(g_wb16 + tbase + off)        = hi;
    *(__nv_bfloat16*)(g_wb16 + tbase + 8192 + off) = lo;
}

// ---------------------------------------------------------------------------
// x pre-split: NCHW fp32 -> [b][h][cp][w] packed bf16 hi/lo
// ---------------------------------------------------------------------------
__global__ __launch_bounds__(256) void prep_x_k(const float* __restrict__ x)
{
    int id = blockIdx.x*256 + threadIdx.x;
    int w = id & 127, cp = (id >> 7) & 31, h = (id >> 12) & 127, b = id >> 19;
    float v0 = x[(((size_t)(b*64 + cp*2    ))*128 + h)*128 + w];
    float v1 = x[(((size_t)(b*64 + cp*2 + 1))*128 + h)*128 + w];
    uint32_t hp, lp;
    split_pack(v0, v1, hp, lp);
    g_xh[id] = hp;
    g_xl[id] = lp;
}

// ---------------------------------------------------------------------------
// Fused 3x3 conv via mma.sync — software pipelined (unchanged R9)
// ---------------------------------------------------------------------------
#define CONV_SMEM (73728 + 133120 + 128)

__global__ __launch_bounds__(256) void conv_mma_k(const float* __restrict__ bq,
                                                  const float* __restrict__ bk,
                                                  const float* __restrict__ bv)
{
    extern __shared__ char sm[];
    char* SW = sm;                     // 18 x 4096
    char* SA = sm + 73728;             // 8 x 16640  [slot*2 + split]
    float* sbias = (float*)(sm + 73728 + 133120);
    const int tid = threadIdx.x, lane = tid & 31, wid = tid >> 5;
    const int b = blockIdx.y;
    const int sel = blockIdx.z >> 1, co0 = (blockIdx.z & 1) * 32;
    const int h0 = blockIdx.x * 8;
    const float* bias = (sel == 0) ? bq : ((sel == 1) ? bk : bv);
    uint32_t* gh = (sel == 0) ? g_qh : ((sel == 1) ? g_kh : g_vh);
    uint32_t* gl = (sel == 0) ? g_ql : ((sel == 1) ? g_kl : g_vl);

    {
        const char* gw = g_wb16 + (size_t)sel*9*2*8192 + (size_t)co0*128;
        for (int i = tid; i < 18*256; i += 256) {
            int t = i >> 8, seg = i & 255;
            *(uint4*)(SW + t*4096 + seg*16) =
                *(const uint4*)(gw + (size_t)t*8192 + seg*16);
        }
    }
    if (tid < 32) sbias[tid] = bias[co0 + tid];
    if (tid < 128) {
        int s8 = tid / 16, k = tid % 16;
        uint32_t off = s8*16640 + ((k < 8) ? 0u : 16512u) + (k & 7)*16;
        *(uint4*)(SA + off) = make_uint4(0,0,0,0);
    }

    for (int rr = -1; rr <= 1; rr++) {
        const int r = h0 + rr;
        const int s = (r + 4) & 3;
        char* hi = SA + (size_t)(s*2 + 0)*16640;
        char* lo = SA + (size_t)(s*2 + 1)*16640;
        const bool valid = ((unsigned)r < 128u);
        const uint32_t* xh = g_xh + (size_t)(b*Hn + (valid ? r : 0))*4096;
        const uint32_t* xl = g_xl + (size_t)(b*Hn + (valid ? r : 0))*4096;
#pragma unroll
        for (int j = 0; j < 16; j++) {
            int id = tid + j*256;
            int w = id & 127, cp = id >> 7;
            uint32_t hv = valid ? xh[id] : 0u;
            uint32_t lv = valid ? xl[id] : 0u;
            uint32_t row = (uint32_t)w + 1;
            uint32_t off = row*128 + (((uint32_t)cp*4) ^ ((row & 7) << 4));
            *(uint32_t*)(hi + off) = hv;
            *(uint32_t*)(lo + off) = lv;
        }
    }
    __syncthreads();

    const uint32_t SAb = smem_u32(SA);
    const uint32_t SWb = smem_u32(SW);
    const int m0 = wid * 16;
    const int aRowSel = lane & 15;
    const int aColSel = (lane & 16) ? 16 : 0;
    const int bRowSel = (lane & 7) + ((lane & 16) ? 8 : 0);
    const int bColSel = (lane & 8) ? 16 : 0;

    uint32_t aAO[3][4], bO[4];
#pragma unroll
    for (int kx = 0; kx < 3; kx++) {
        const int arow = m0 + kx + aRowSel;
        const uint32_t axor = ((uint32_t)arow & 7) << 4;
#pragma unroll
        for (int cc = 0; cc < 4; cc++)
            aAO[kx][cc] = (uint32_t)arow*128 + (((uint32_t)(cc*32 + aColSel)) ^ axor);
    }
    {
        const uint32_t bxor = ((uint32_t)bRowSel & 7) << 4;
#pragma unroll
        for (int cc = 0; cc < 4; cc++)
            bO[cc] = (uint32_t)bRowSel*128 + (((uint32_t)(cc*32 + bColSel)) ^ bxor);
    }

    for (int hh = 0; hh < 8; hh++) {
        const int h = h0 + hh;

        uint32_t ph[16], pl[16];
        const bool pf = (hh < 7);
        if (pf) {
            const int rn = h + 2;
            const bool valid = rn < 128;
            const uint32_t* xh = g_xh + (size_t)(b*Hn + (valid ? rn : 0))*4096;
            const uint32_t* xl = g_xl + (size_t)(b*Hn + (valid ? rn : 0))*4096;
#pragma unroll
            for (int j = 0; j < 16; j++) {
                int id = tid + j*256;
                ph[j] = valid ? xh[id] : 0u;
                pl[j] = valid ? xl[id] : 0u;
            }
        }

        float acc[4][4];
#pragma unroll
        for (int i = 0; i < 4; i++)
#pragma unroll
            for (int j = 0; j < 4; j++) acc[i][j] = 0.f;

#pragma unroll
        for (int ky = 0; ky < 3; ky++) {
            const int r = h + ky - 1;
            const int s = (r + 4) & 3;
            const uint32_t Ahi = SAb + (uint32_t)(s*2)*16640;
            const uint32_t Alo = Ahi + 16640;
#pragma unroll
            for (int kx = 0; kx < 3; kx++) {
                const uint32_t Wt = SWb + (uint32_t)((ky*3 + kx)*2)*4096;
#pragma unroll
                for (int cc = 0; cc < 4; cc++) {
                    uint32_t ah[4], al[4], bh[8], bl[8];
                    ldsm4(ah, Ahi + aAO[kx][cc]);
                    ldsm4(al, Alo + aAO[kx][cc]);
                    ldsm4(bh + 0, Wt + bO[cc]);
                    ldsm4(bh + 4, Wt + bO[cc] + 2048);
                    ldsm4(bl + 0, Wt + 4096 + bO[cc]);
                    ldsm4(bl + 4, Wt + 4096 + bO[cc] + 2048);
#pragma unroll
                    for (int nt = 0; nt < 4; nt++) {
                        mma16816(acc[nt], ah, bh[nt*2], bh[nt*2 + 1]);
                        mma16816(acc[nt], al, bh[nt*2], bh[nt*2 + 1]);
                        mma16816(acc[nt], ah, bl[nt*2], bl[nt*2 + 1]);
                    }
                }
            }
        }

        if (pf) {
            const int s = (h + 2 + 4) & 3;
            char* hi = SA + (size_t)(s*2 + 0)*16640;
            char* lo = SA + (size_t)(s*2 + 1)*16640;
#pragma unroll
            for (int j = 0; j < 16; j++) {
                int id = tid + j*256;
                int w = id & 127, cp = id >> 7;
                uint32_t row = (uint32_t)w + 1;
                uint32_t off = row*128 + (((uint32_t)cp*4) ^ ((row & 7) << 4));
                *(uint32_t*)(hi + off) = ph[j];
                *(uint32_t*)(lo + off) = pl[j];
            }
        }

        const int wr = m0 + (lane >> 2);
        const int cb = (lane & 3) * 2;
        const size_t rowBase = (size_t)(b*Hn + h)*Wn;
#pragma unroll
        for (int nt = 0; nt < 4; nt++) {
            const int c = co0 + nt*8 + cb;
            const float b0 = sbias[nt*8 + cb], b1 = sbias[nt*8 + cb + 1];
            uint32_t hp, lp;
            split_pack(acc[nt][0] + b0, acc[nt][1] + b1, hp, lp);
            gh[(rowBase + wr)*32 + (c >> 1)] = hp;
            gl[(rowBase + wr)*32 + (c >> 1)] = lp;
            split_pack(acc[nt][2] + b0, acc[nt][3] + b1, hp, lp);
            gh[(rowBase + wr + 8)*32 + (c >> 1)] = hp;
            gl[(rowBase + wr + 8)*32 + (c >> 1)] = lp;
        }
        __syncthreads();
    }
}

// ---------------------------------------------------------------------------
// FUSED attention (flash style), register-trimmed for 2 CTAs/SM.
// blockIdx.z: 0 = eH->out_H per (w,b), 1 = eW->out_W per (h,b).
// ---------------------------------------------------------------------------
#define FUSED_SMEM (4*16384 + 4*8192)

__global__ __launch_bounds__(256, 2) void fused_attn_k()
{
    extern __shared__ char sm[];
    char* QH = sm;            char* QL = sm + 16384;
    char* KH = sm + 32768;    char* KL = sm + 49152;
    char* VTH0 = sm + 65536;  char* VTH1 = sm + 73728;
    char* VTL0 = sm + 81920;  char* VTL1 = sm + 90112;
    const int tid = threadIdx.x, lane = tid & 31, wid = tid >> 5;
    const int p = blockIdx.x, b = blockIdx.y, mode = blockIdx.z;

    const size_t base32 = mode ? (size_t)((b*Hn + p)*Wn)*32
                               : (size_t)(b*Hn*Wn + p)*32;
    const int str32 = mode ? 32 : Wn*32;

    // Stage Q,K hi/lo
    for (int i = tid; i < 8192; i += 256) {
        int tsel = i >> 12, rem = i & 4095;
        int cp = rem & 31, r = rem >> 5;
        const uint32_t* sh = tsel ? g_kh : g_qh;
        const uint32_t* sl = tsel ? g_kl : g_ql;
        uint32_t hv = sh[base32 + (size_t)r*str32 + cp];
        uint32_t lv = sl[base32 + (size_t)r*str32 + cp];
        uint32_t off = (uint32_t)r*128 + (((uint32_t)cp*4) ^ (((uint32_t)r & 7) << 4));
        *(uint32_t*)((tsel ? KH : QH) + off) = hv;
        *(uint32_t*)((tsel ? KL : QL) + off) = lv;
    }
    // Stage V transposed: VT[c][g] hi/lo
    for (int i = tid; i < 4096; i += 256) {
        int cp = i & 31, g = i >> 5;
        uint32_t hv = g_vh[base32 + (size_t)g*str32 + cp];
        uint32_t lv = g_vl[base32 + (size_t)g*str32 + cp];
        int t = g >> 6, gin = g & 63;
        int c0 = cp*2, c1 = cp*2 + 1;
        uint32_t off0 = (uint32_t)c0*128 + (((uint32_t)gin*2) ^ (((uint32_t)c0 & 7) << 4));
        uint32_t off1 = (uint32_t)c1*128 + (((uint32_t)gin*2) ^ (((uint32_t)c1 & 7) << 4));
        *(uint16_t*)((t ? VTH1 : VTH0) + off0) = (uint16_t)(hv & 0xFFFF);
        *(uint16_t*)((t ? VTH1 : VTH0) + off1) = (uint16_t)(hv >> 16);
        *(uint16_t*)((t ? VTL1 : VTL0) + off0) = (uint16_t)(lv & 0xFFFF);
        *(uint16_t*)((t ? VTL1 : VTL0) + off1) = (uint16_t)(lv >> 16);
    }
    __syncthreads();

    const uint32_t QHb = smem_u32(QH), QLb = smem_u32(QL);
    const uint32_t KHb = smem_u32(KH), KLb = smem_u32(KL);
    const uint32_t VTH0b = smem_u32(VTH0), VTH1b = smem_u32(VTH1);
    const uint32_t VTL0b = smem_u32(VTL0), VTL1b = smem_u32(VTL1);
    const int m0 = wid * 16;
    const int aRowSel = lane & 15;
    const int aColSel = (lane & 16) ? 16 : 0;
    const int bRowSel = (lane & 7) + ((lane & 16) ? 8 : 0);
    const int bColSel = (lane & 8) ? 16 : 0;

    uint32_t aO[4], bO[4];
    {
        const int arow = m0 + aRowSel;
        const uint32_t axor = ((uint32_t)arow & 7) << 4;
        const uint32_t bxor = ((uint32_t)bRowSel & 7) << 4;
#pragma unroll
        for (int kc = 0; kc < 4; kc++) {
            aO[kc] = (uint32_t)arow*128 + (((uint32_t)(kc*32 + aColSel)) ^ axor);
            bO[kc] = (uint32_t)bRowSel*128 + (((uint32_t)(kc*32 + bColSel)) ^ bxor);
        }
    }

    // ---- Phase 1: logits 128x128 -> acc (B-frags loaded in small chunks) ----
    float acc[16][4];
#pragma unroll
    for (int i = 0; i < 16; i++)
#pragma unroll
        for (int j = 0; j < 4; j++) acc[i][j] = 0.f;

#pragma unroll
    for (int kc = 0; kc < 4; kc++) {
        uint32_t ah[4], al[4];
        ldsm4(ah, QHb + aO[kc]);
        ldsm4(al, QLb + aO[kc]);
#pragma unroll
        for (int t8 = 0; t8 < 8; t8++) {            // 8 row-blocks of K tile
            uint32_t bh[4], bl[4];
            const uint32_t boff = bO[kc] + (uint32_t)t8*2048;
            ldsm4(bh, KHb + boff);
            ldsm4(bl, KLb + boff);
#pragma unroll
            for (int j = 0; j < 2; j++) {
                const int a = t8*2 + j;
                mma16816(acc[a], ah, bh[j*2], bh[j*2 + 1]);
                mma16816(acc[a], al, bh[j*2], bh[j*2 + 1]);
                mma16816(acc[a], ah, bl[j*2], bl[j*2 + 1]);
            }
        }
    }

    // ---- Phase 2: mask + local softmax + e = exp(l - m) in place ----
    const int msBase = mode ? (b*Hn + p)*Wn : b*Hn*Wn + p;
    const int msStr  = mode ? 1 : Wn;
    float2* msOut = mode ? g_msW : g_msH;

#pragma unroll
    for (int half2 = 0; half2 < 2; half2++) {
        const int row = m0 + (lane >> 2) + half2*8;
        if (!mode) {
#pragma unroll
            for (int nt = 0; nt < 16; nt++) {
                const int g = nt*8 + (lane & 3)*2;
                if (row == g)     acc[nt][half2*2 + 0] = -CUDART_INF_F;
                if (row == g + 1) acc[nt][half2*2 + 1] = -CUDART_INF_F;
            }
        }
        float m = acc[0][half2*2];
#pragma unroll
        for (int nt = 0; nt < 16; nt++) {
            m = fmaxf(m, acc[nt][half2*2 + 0]);
            m = fmaxf(m, acc[nt][half2*2 + 1]);
        }
        m = fmaxf(m, __shfl_xor_sync(~0u, m, 1));
        m = fmaxf(m, __shfl_xor_sync(~0u, m, 2));
        float s = 0.f;
#pragma unroll
        for (int nt = 0; nt < 16; nt++) {
            float e0 = __expf(acc[nt][half2*2 + 0] - m);
            float e1 = __expf(acc[nt][half2*2 + 1] - m);
            acc[nt][half2*2 + 0] = e0;
            acc[nt][half2*2 + 1] = e1;
            s += e0 + e1;
        }
        s += __shfl_xor_sync(~0u, s, 1);
        s += __shfl_xor_sync(~0u, s, 2);
        if ((lane & 3) == 0) msOut[msBase + row*msStr] = make_float2(m, s);
    }

    // ---- Pack P fragments in place (acc dies as ap is born) ----
    uint32_t ap[64];
#pragma unroll
    for (int kc = 0; kc < 8; kc++) {
        split_pack(acc[2*kc    ][0], acc[2*kc    ][1], ap[kc*8 + 0], ap[kc*8 + 4]);
        split_pack(acc[2*kc    ][2], acc[2*kc    ][3], ap[kc*8 + 1], ap[kc*8 + 5]);
        split_pack(acc[2*kc + 1][0], acc[2*kc + 1][1], ap[kc*8 + 2], ap[kc*8 + 6]);
        split_pack(acc[2*kc + 1][2], acc[2*kc + 1][3], ap[kc*8 + 3], ap[kc*8 + 7]);
    }

    // ---- Phase 3: out partial = P * V (B-frags chunked) ----
    float acc2[8][4];
#pragma unroll
    for (int i = 0; i < 8; i++)
#pragma unroll
        for (int j = 0; j < 4; j++) acc2[i][j] = 0.f;

#pragma unroll
    for (int kc = 0; kc < 8; kc++) {
        const uint32_t (&aH)[4] = *reinterpret_cast<const uint32_t(*)[4]>(ap + kc*8);
        const uint32_t (&aL)[4] = *reinterpret_cast<const uint32_t(*)[4]>(ap + kc*8 + 4);
        const uint32_t Bh = (kc < 4) ? VTH0b : VTH1b;
        const uint32_t Bl = (kc < 4) ? VTL0b : VTL1b;
        const int cc = kc & 3;
#pragma unroll
        for (int t4 = 0; t4 < 4; t4++) {
            uint32_t bh[4], bl[4];
            const uint32_t boff = bO[cc] + (uint32_t)t4*2048;
            ldsm4(bh, Bh + boff);
            ldsm4(bl, Bl + boff);
#pragma unroll
            for (int j = 0; j < 2; j++) {
                const int nt = t4*2 + j;
                mma16816(acc2[nt], aH, bh[j*2], bh[j*2 + 1]);
                mma16816(acc2[nt], aL, bh[j*2], bh[j*2 + 1]);
                mma16816(acc2[nt], aH, bl[j*2], bl[j*2 + 1]);
            }
        }
    }

    // ---- Epilogue: unnormalized partials ----
    float* oB = (mode ? g_oW : g_oH) + ((size_t)(b*Hn + p)*Wn)*Cn;
#pragma unroll
    for (int half2 = 0; half2 < 2; half2++) {
        const int row = m0 + (lane >> 2) + half2*8;
#pragma unroll
        for (int nt = 0; nt < 8; nt++) {
            const int c = nt*8 + (lane & 3)*2;
            *(float2*)&oB[(size_t)row*Cn + c] =
                make_float2(acc2[nt][half2*2 + 0], acc2[nt][half2*2 + 1]);
        }
    }
}

// ---------------------------------------------------------------------------
// Combine (m, s) halves -> per-pixel (alphaH, alphaW)
// ---------------------------------------------------------------------------
__global__ __launch_bounds__(256) void combine_ms_k()
{
    int i = blockIdx.x*256 + threadIdx.x;
    float2 a = g_msH[i], c = g_msW[i];
    float m = fmaxf(a.x, c.x);
    float eH = __expf(a.x - m), eW = __expf(c.x - m);
    float inv = 1.0f / (a.y*eH + c.y*eW);
    g_al[i] = make_float2(eH*inv, eW*inv);
}

// ---------------------------------------------------------------------------
// Final: out[b][c][h][w] = gamma*(oHp*aH + oWp*aW) + x
// ---------------------------------------------------------------------------
__global__ __launch_bounds__(256) void final_k(const float* __restrict__ x,
                                               const float* __restrict__ gamma,
                                               float* __restrict__ out)
{
    __shared__ float s[Cn][33];
    __shared__ float2 al[32];
    const int w0 = blockIdx.x*32, h = blockIdx.y, b = blockIdx.z;
    const float g = gamma[0];
    if (threadIdx.x < 32)
        al[threadIdx.x] = g_al[(b*Hn + h)*Wn + w0 + threadIdx.x];
    __syncthreads();
    for (int i = threadIdx.x; i < 32*Cn; i += 256) {
        int wl = i >> 6, c = i & 63;
        float a = g_oH[(((size_t)b*Wn + (w0+wl))*Hn + h)*Cn + c];
        float d = g_oW[(((size_t)b*Hn + h)*Wn + (w0+wl))*Cn + c];
        float2 av = al[wl];
        s[c][wl] = g*(a*av.x + d*av.y);
    }
    __syncthreads();
    for (int i = threadIdx.x; i < Cn*32; i += 256) {
        int c = i >> 5, wl = i & 31;
        size_t idx = (((size_t)b*Cn + c)*Hn + h)*Wn + w0 + wl;
        out[idx] = s[c][wl] + x[idx];
    }
}

// ---------------------------------------------------------------------------
extern "C" void kernel_launch(void* const* d_in, const int* in_sizes, int n_in,
                              void* d_out, int out_size)
{
    (void)in_sizes; (void)n_in; (void)out_size;
    const float* x     = (const float*)d_in[0];
    const float* Wq    = (const float*)d_in[1];
    const float* bq    = (const float*)d_in[2];
    const float* Wk    = (const float*)d_in[3];
    const float* bk    = (const float*)d_in[4];
    const float* Wv    = (const float*)d_in[5];
    const float* bv    = (const float*)d_in[6];
    const float* gamma = (const float*)d_in[7];
    float* out = (float*)d_out;

    static bool attr_set = false;
    if (!attr_set) {
        cudaFuncSetAttribute(conv_mma_k, cudaFuncAttributeMaxDynamicSharedMemorySize,
                             CONV_SMEM);
        cudaFuncSetAttribute(fused_attn_k, cudaFuncAttributeMaxDynamicSharedMemorySize,
                             FUSED_SMEM);
        attr_set = true;
    }

    prep_w_k<<<(3*3*3*64*64 + 255)/256, 256>>>(Wq, Wk, Wv);
    prep_x_k<<<(Bn*Hn*32*Wn)/256, 256>>>(x);

    dim3 grid_conv(16, Bn, 6);   // (htile, b, sel*2 + co-half)
    conv_mma_k<<<grid_conv, 256, CONV_SMEM>>>(bq, bk, bv);

    dim3 grid_at(128, Bn, 2);    // (p, b, mode)
    fused_attn_k<<<grid_at, 256, FUSED_SMEM>>>();

    combine_ms_k<<<(Bn*Hn*Wn)/256, 256>>>();

    dim3 grid_fin(Wn/32, Hn, Bn);
    final_k<<<grid_fin, 256>>>(x, gamma, out);
}

// round 13
// speedup vs baseline: 1.4999x; 1.2228x over previous
#include <cuda_runtime.h>
#include <cuda_fp16.h>
#include <math_constants.h>
#include <cstdint>

#define Bn 8
#define Cn 64
#define Hn 128
#define Wn 128

// ---------------------------------------------------------------------------
// Global scratch (no allocation allowed)
// q: fp16 hi+lo packed pairs; k,v: fp16 hi only. x: fp16 hi/lo.
// ---------------------------------------------------------------------------
__device__ uint32_t g_qh[Bn*Hn*Wn*32], g_ql[Bn*Hn*Wn*32];
__device__ uint32_t g_kh[Bn*Hn*Wn*32];
__device__ uint32_t g_vh[Bn*Hn*Wn*32];
__device__ uint32_t g_xh[Bn*Hn*32*Wn], g_xl[Bn*Hn*32*Wn];
__device__ float g_oH[Bn*Hn*Wn*Cn];         // [b][w][h][c]  (unnormalized)
__device__ float g_oW[Bn*Hn*Wn*Cn];         // [b][h][w][c]  (unnormalized)
__device__ float2 g_msH[Bn*Hn*Wn];
__device__ float2 g_msW[Bn*Hn*Wn];
__device__ float2 g_al[Bn*Hn*Wn];
// fp16 weight tiles (hi only), [sel][ky][kx] full-co tiles [64co][64ci], 8KB
__device__ __align__(16) char g_wf16[3*3*3*8192];

// ---------------------------------------------------------------------------
// helpers
// ---------------------------------------------------------------------------
__device__ __forceinline__ uint32_t smem_u32(const void* p) {
    uint32_t a;
    asm("{ .reg .u64 t; cvta.to.shared.u64 t, %1; cvt.u32.u64 %0, t; }"
        : "=r"(a) : "l"(p));
    return a;
}
__device__ __forceinline__ void ldsm4(uint32_t* r, uint32_t addr) {
    asm volatile("ldmatrix.sync.aligned.m8n8.x4.shared.b16 {%0,%1,%2,%3}, [%4];"
        : "=r"(r[0]), "=r"(r[1]), "=r"(r[2]), "=r"(r[3]) : "r"(addr));
}
__device__ __forceinline__ void mma16816(float (&d)[4], const uint32_t (&a)[4],
                                         uint32_t b0, uint32_t b1) {
    asm volatile("mma.sync.aligned.m16n8k16.row.col.f32.f16.f16.f32 "
        "{%0,%1,%2,%3}, {%4,%5,%6,%7}, {%8,%9}, {%0,%1,%2,%3};"
        : "+f"(d[0]), "+f"(d[1]), "+f"(d[2]), "+f"(d[3])
        : "r"(a[0]), "r"(a[1]), "r"(a[2]), "r"(a[3]), "r"(b0), "r"(b1));
}
__device__ __forceinline__ void split_pack(float a, float b,
                                           uint32_t& hp, uint32_t& lp) {
    __half ha = __float2half_rn(a), hb = __float2half_rn(b);
    __half la = __float2half_rn(a - __half2float(ha));
    __half lb = __float2half_rn(b - __half2float(hb));
    hp = ((uint32_t)__half_as_ushort(hb) << 16) | __half_as_ushort(ha);
    lp = ((uint32_t)__half_as_ushort(lb) << 16) | __half_as_ushort(la);
}

// ---------------------------------------------------------------------------
// Weight prep: OIHW fp32 -> fp16 full-co tiles, 128B rows swizzled
// ---------------------------------------------------------------------------
__global__ void prep_w_k(const float* __restrict__ Wq,
                         const float* __restrict__ Wk,
                         const float* __restrict__ Wv)
{
    int i = blockIdx.x*blockDim.x + threadIdx.x;
    if (i >= 3*3*3*64*64) return;
    int ci = i & 63; int t = i >> 6;
    int co = t & 63; t >>= 6;
    int kx = t % 3;  t /= 3;
    int ky = t % 3;  t /= 3;
    int sel = t;
    const float* Ws = (sel == 0) ? Wq : ((sel == 1) ? Wk : Wv);
    float v = Ws[((co*Cn + ci)*3 + ky)*3 + kx];
    size_t tbase = (size_t)(((sel*3 + ky)*3 + kx))*8192;
    uint32_t off = (uint32_t)co*128 + (((uint32_t)ci*2) ^ (((uint32_t)co & 7) << 4));
    *(__half*)(g_wf16 + tbase + off) = __float2half_rn(v);
}

// ---------------------------------------------------------------------------
// x pre-split: NCHW fp32 -> [b][h][cp][w] packed fp16 hi/lo
// ---------------------------------------------------------------------------
__global__ __launch_bounds__(256) void prep_x_k(const float* __restrict__ x)
{
    int id = blockIdx.x*256 + threadIdx.x;
    int w = id & 127, cp = (id >> 7) & 31, h = (id >> 12) & 127, b = id >> 19;
    float v0 = x[(((size_t)(b*64 + cp*2    ))*128 + h)*128 + w];
    float v1 = x[(((size_t)(b*64 + cp*2 + 1))*128 + h)*128 + w];
    uint32_t hp, lp;
    split_pack(v0, v1, hp, lp);
    g_xh[id] = hp;
    g_xl[id] = lp;
}

// ---------------------------------------------------------------------------
// Fused 3x3 conv via mma.sync fp16 (x split hi/lo, w single) — 512 threads,
// full co per CTA (warps 0-7: co 0..31, warps 8-15: co 32..63).
// Software pipelined 4-slot ring, 1 sync/iter.
// ---------------------------------------------------------------------------
#define CONV_SMEM (73728 + 133120 + 256)

__global__ __launch_bounds__(512, 1) void conv_mma_k(const float* __restrict__ bq,
                                                     const float* __restrict__ bk,
                                                     const float* __restrict__ bv)
{
    extern __shared__ char sm[];
    char* SW = sm;                     // 9 x 8192 (full-co fp16 tiles)
    char* SA = sm + 73728;             // 8 x 16640 [slot*2 + split]
    float* sbias = (float*)(sm + 73728 + 133120);   // 64 floats
    const int tid = threadIdx.x, lane = tid & 31, wid = tid >> 5;
    const int b = blockIdx.y;
    const int sel = blockIdx.z;
    const int h0 = blockIdx.x * 8;
    const float* bias = (sel == 0) ? bq : ((sel == 1) ? bk : bv);
    uint32_t* gh = (sel == 0) ? g_qh : ((sel == 1) ? g_kh : g_vh);

    // Stage weights: 9 x 8KB
    {
        const uint4* gw = (const uint4*)(g_wf16 + (size_t)sel*9*8192);
        for (int i = tid; i < 4608; i += 512)
            *(uint4*)(SW + i*16) = gw[i];
    }
    if (tid < 64) sbias[tid] = bias[tid];
    // Zero boundary rows (w=-1 row 0, w=128 row 129) of all 8 slot-split tiles
    if (tid < 128) {
        int s8 = tid / 16, k = tid % 16;
        uint32_t off = s8*16640 + ((k < 8) ? 0u : 16512u) + (k & 7)*16;
        *(uint4*)(SA + off) = make_uint4(0,0,0,0);
    }

    // Prologue: stage rows h0-1..h0+1
    for (int rr = -1; rr <= 1; rr++) {
        const int r = h0 + rr;
        const int s = (r + 4) & 3;
        char* hi = SA + (size_t)(s*2 + 0)*16640;
        char* lo = SA + (size_t)(s*2 + 1)*16640;
        const bool valid = ((unsigned)r < 128u);
        const uint32_t* xh = g_xh + (size_t)(b*Hn + (valid ? r : 0))*4096;
        const uint32_t* xl = g_xl + (size_t)(b*Hn + (valid ? r : 0))*4096;
#pragma unroll
        for (int j = 0; j < 8; j++) {
            int id = tid + j*512;
            int w = id & 127, cp = id >> 7;
            uint32_t hv = valid ? xh[id] : 0u;
            uint32_t lv = valid ? xl[id] : 0u;
            uint32_t row = (uint32_t)w + 1;
            uint32_t off = row*128 + (((uint32_t)cp*4) ^ ((row & 7) << 4));
            *(uint32_t*)(hi + off) = hv;
            *(uint32_t*)(lo + off) = lv;
        }
    }
    __syncthreads();

    const uint32_t SAb = smem_u32(SA);
    const uint32_t SWb = smem_u32(SW);
    const int m0 = (wid & 7) * 16;
    const int nh = wid >> 3;           // co half
    const int aRowSel = lane & 15;
    const int aColSel = (lane & 16) ? 16 : 0;
    const int bRowSel = (lane & 7) + ((lane & 16) ? 8 : 0);
    const int bColSel = (lane & 8) ? 16 : 0;

    uint32_t aAO[3][4], bO[4];
#pragma unroll
    for (int kx = 0; kx < 3; kx++) {
        const int arow = m0 + kx + aRowSel;
        const uint32_t axor = ((uint32_t)arow & 7) << 4;
#pragma unroll
        for (int cc = 0; cc < 4; cc++)
            aAO[kx][cc] = (uint32_t)arow*128 + (((uint32_t)(cc*32 + aColSel)) ^ axor);
    }
    {
        const int brow = nh*32 + bRowSel;
        const uint32_t bxor = ((uint32_t)brow & 7) << 4;
#pragma unroll
        for (int cc = 0; cc < 4; cc++)
            bO[cc] = (uint32_t)brow*128 + (((uint32_t)(cc*32 + bColSel)) ^ bxor);
    }

    for (int hh = 0; hh < 8; hh++) {
        const int h = h0 + hh;

        uint32_t ph[8], pl[8];
        const bool pf = (hh < 7);
        if (pf) {
            const int rn = h + 2;
            const bool valid = rn < 128;
            const uint32_t* xh = g_xh + (size_t)(b*Hn + (valid ? rn : 0))*4096;
            const uint32_t* xl = g_xl + (size_t)(b*Hn + (valid ? rn : 0))*4096;
#pragma unroll
            for (int j = 0; j < 8; j++) {
                int id = tid + j*512;
                ph[j] = valid ? xh[id] : 0u;
                pl[j] = valid ? xl[id] : 0u;
            }
        }

        float acc[4][4];
#pragma unroll
        for (int i = 0; i < 4; i++)
#pragma unroll
            for (int j = 0; j < 4; j++) acc[i][j] = 0.f;

#pragma unroll
        for (int ky = 0; ky < 3; ky++) {
            const int r = h + ky - 1;
            const int s = (r + 4) & 3;
            const uint32_t Ahi = SAb + (uint32_t)(s*2)*16640;
            const uint32_t Alo = Ahi + 16640;
#pragma unroll
            for (int kx = 0; kx < 3; kx++) {
                const uint32_t Wt = SWb + (uint32_t)((ky*3 + kx))*8192;
#pragma unroll
                for (int cc = 0; cc < 4; cc++) {
                    uint32_t ah[4], al[4], bh[8];
                    ldsm4(ah, Ahi + aAO[kx][cc]);
                    ldsm4(al, Alo + aAO[kx][cc]);
                    ldsm4(bh + 0, Wt + bO[cc]);
                    ldsm4(bh + 4, Wt + bO[cc] + 2048);
#pragma unroll
                    for (int nt = 0; nt < 4; nt++) {
                        mma16816(acc[nt], ah, bh[nt*2], bh[nt*2 + 1]);
                        mma16816(acc[nt], al, bh[nt*2], bh[nt*2 + 1]);
                    }
                }
            }
        }

        if (pf) {
            const int s = (h + 2 + 4) & 3;
            char* hi = SA + (size_t)(s*2 + 0)*16640;
            char* lo = SA + (size_t)(s*2 + 1)*16640;
#pragma unroll
            for (int j = 0; j < 8; j++) {
                int id = tid + j*512;
                int w = id & 127, cp = id >> 7;
                uint32_t row = (uint32_t)w + 1;
                uint32_t off = row*128 + (((uint32_t)cp*4) ^ ((row & 7) << 4));
                *(uint32_t*)(hi + off) = ph[j];
                *(uint32_t*)(lo + off) = pl[j];
            }
        }

        // Epilogue: q gets hi+lo; k/v hi only
        const int wr = m0 + (lane >> 2);
        const int cb = (lane & 3) * 2;
        const size_t rowBase = (size_t)(b*Hn + h)*Wn;
#pragma unroll
        for (int nt = 0; nt < 4; nt++) {
            const int c = nh*32 + nt*8 + cb;
            const float b0 = sbias[c], b1 = sbias[c + 1];
            uint32_t hp, lp;
            split_pack(acc[nt][0] + b0, acc[nt][1] + b1, hp, lp);
            gh[(rowBase + wr)*32 + (c >> 1)] = hp;
            if (sel == 0) g_ql[(rowBase + wr)*32 + (c >> 1)] = lp;
            split_pack(acc[nt][2] + b0, acc[nt][3] + b1, hp, lp);
            gh[(rowBase + wr + 8)*32 + (c >> 1)] = hp;
            if (sel == 0) g_ql[(rowBase + wr + 8)*32 + (c >> 1)] = lp;
        }
        __syncthreads();
    }
}

// ---------------------------------------------------------------------------
// FUSED attention, fp16 (Q/P split hi/lo, K/V single).
// blockIdx.z: 0 = eH->out_H per (w,b), 1 = eW->out_W per (h,b).
// ---------------------------------------------------------------------------
#define FUSED_SMEM (3*16384 + 2*8192)

__global__ __launch_bounds__(256, 2) void fused_attn_k()
{
    extern __shared__ char sm[];
    char* QH = sm;            char* QL = sm + 16384;
    char* KH = sm + 32768;
    char* VTH0 = sm + 49152;  char* VTH1 = sm + 57344;
    const int tid = threadIdx.x, lane = tid & 31, wid = tid >> 5;
    const int p = blockIdx.x, b = blockIdx.y, mode = blockIdx.z;

    const size_t base32 = mode ? (size_t)((b*Hn + p)*Wn)*32
                               : (size_t)(b*Hn*Wn + p)*32;
    const int str32 = mode ? 32 : Wn*32;

    // Stage Q hi/lo
    for (int i = tid; i < 4096; i += 256) {
        int cp = i & 31, r = i >> 5;
        uint32_t off = (uint32_t)r*128 + (((uint32_t)cp*4) ^ (((uint32_t)r & 7) << 4));
        *(uint32_t*)(QH + off) = g_qh[base32 + (size_t)r*str32 + cp];
        *(uint32_t*)(QL + off) = g_ql[base32 + (size_t)r*str32 + cp];
    }
    // Stage K hi
    for (int i = tid; i < 4096; i += 256) {
        int cp = i & 31, r = i >> 5;
        uint32_t off = (uint32_t)r*128 + (((uint32_t)cp*4) ^ (((uint32_t)r & 7) << 4));
        *(uint32_t*)(KH + off) = g_kh[base32 + (size_t)r*str32 + cp];
    }
    // Stage V transposed hi: VT[c][g]
    for (int i = tid; i < 4096; i += 256) {
        int cp = i & 31, g = i >> 5;
        uint32_t hv = g_vh[base32 + (size_t)g*str32 + cp];
        int t = g >> 6, gin = g & 63;
        int c0 = cp*2, c1 = cp*2 + 1;
        uint32_t off0 = (uint32_t)c0*128 + (((uint32_t)gin*2) ^ (((uint32_t)c0 & 7) << 4));
        uint32_t off1 = (uint32_t)c1*128 + (((uint32_t)gin*2) ^ (((uint32_t)c1 & 7) << 4));
        *(uint16_t*)((t ? VTH1 : VTH0) + off0) = (uint16_t)(hv & 0xFFFF);
        *(uint16_t*)((t ? VTH1 : VTH0) + off1) = (uint16_t)(hv >> 16);
    }
    __syncthreads();

    const uint32_t QHb = smem_u32(QH), QLb = smem_u32(QL);
    const uint32_t KHb = smem_u32(KH);
    const uint32_t VTH0b = smem_u32(VTH0), VTH1b = smem_u32(VTH1);
    const int m0 = wid * 16;
    const int aRowSel = lane & 15;
    const int aColSel = (lane & 16) ? 16 : 0;
    const int bRowSel = (lane & 7) + ((lane & 16) ? 8 : 0);
    const int bColSel = (lane & 8) ? 16 : 0;

    uint32_t aO[4], bO[4];
    {
        const int arow = m0 + aRowSel;
        const uint32_t axor = ((uint32_t)arow & 7) << 4;
        const uint32_t bxor = ((uint32_t)bRowSel & 7) << 4;
#pragma unroll
        for (int kc = 0; kc < 4; kc++) {
            aO[kc] = (uint32_t)arow*128 + (((uint32_t)(kc*32 + aColSel)) ^ axor);
            bO[kc] = (uint32_t)bRowSel*128 + (((uint32_t)(kc*32 + bColSel)) ^ bxor);
        }
    }

    // ---- Phase 1: logits 128x128 ----
    float acc[16][4];
#pragma unroll
    for (int i = 0; i < 16; i++)
#pragma unroll
        for (int j = 0; j < 4; j++) acc[i][j] = 0.f;

#pragma unroll
    for (int kc = 0; kc < 4; kc++) {
        uint32_t ah[4], al[4];
        ldsm4(ah, QHb + aO[kc]);
        ldsm4(al, QLb + aO[kc]);
#pragma unroll
        for (int t8 = 0; t8 < 8; t8++) {
            uint32_t bh[4];
            ldsm4(bh, KHb + bO[kc] + (uint32_t)t8*2048);
#pragma unroll
            for (int j = 0; j < 2; j++) {
                const int a = t8*2 + j;
                mma16816(acc[a], ah, bh[j*2], bh[j*2 + 1]);
                mma16816(acc[a], al, bh[j*2], bh[j*2 + 1]);
            }
        }
    }

    // ---- Phase 2: mask + local softmax + e = exp(l - m) in place ----
    const int msBase = mode ? (b*Hn + p)*Wn : b*Hn*Wn + p;
    const int msStr  = mode ? 1 : Wn;
    float2* msOut = mode ? g_msW : g_msH;

#pragma unroll
    for (int half2 = 0; half2 < 2; half2++) {
        const int row = m0 + (lane >> 2) + half2*8;
        if (!mode) {
#pragma unroll
            for (int nt = 0; nt < 16; nt++) {
                const int g = nt*8 + (lane & 3)*2;
                if (row == g)     acc[nt][half2*2 + 0] = -CUDART_INF_F;
                if (row == g + 1) acc[nt][half2*2 + 1] = -CUDART_INF_F;
            }
        }
        float m = acc[0][half2*2];
#pragma unroll
        for (int nt = 0; nt < 16; nt++) {
            m = fmaxf(m, acc[nt][half2*2 + 0]);
            m = fmaxf(m, acc[nt][half2*2 + 1]);
        }
        m = fmaxf(m, __shfl_xor_sync(~0u, m, 1));
        m = fmaxf(m, __shfl_xor_sync(~0u, m, 2));
        float s = 0.f;
#pragma unroll
        for (int nt = 0; nt < 16; nt++) {
            float e0 = __expf(acc[nt][half2*2 + 0] - m);
            float e1 = __expf(acc[nt][half2*2 + 1] - m);
            acc[nt][half2*2 + 0] = e0;
            acc[nt][half2*2 + 1] = e1;
            s += e0 + e1;
        }
        s += __shfl_xor_sync(~0u, s, 1);
        s += __shfl_xor_sync(~0u, s, 2);
        if ((lane & 3) == 0) msOut[msBase + row*msStr] = make_float2(m, s);
    }

    // ---- Pack P fragments (fp16 hi/lo) in place ----
    uint32_t ap[64];
#pragma unroll
    for (int kc = 0; kc < 8; kc++) {
        split_pack(acc[2*kc    ][0], acc[2*kc    ][1], ap[kc*8 + 0], ap[kc*8 + 4]);
        split_pack(acc[2*kc    ][2], acc[2*kc    ][3], ap[kc*8 + 1], ap[kc*8 + 5]);
        split_pack(acc[2*kc + 1][0], acc[2*kc + 1][1], ap[kc*8 + 2], ap[kc*8 + 6]);
        split_pack(acc[2*kc + 1][2], acc[2*kc + 1][3], ap[kc*8 + 3], ap[kc*8 + 7]);
    }

    // ---- Phase 3: out partial = P * V ----
    float acc2[8][4];
#pragma unroll
    for (int i = 0; i < 8; i++)
#pragma unroll
        for (int j = 0; j < 4; j++) acc2[i][j] = 0.f;

#pragma unroll
    for (int kc = 0; kc < 8; kc++) {
        const uint32_t (&aH)[4] = *reinterpret_cast<const uint32_t(*)[4]>(ap + kc*8);
        const uint32_t (&aL)[4] = *reinterpret_cast<const uint32_t(*)[4]>(ap + kc*8 + 4);
        const uint32_t Bh = (kc < 4) ? VTH0b : VTH1b;
        const int cc = kc & 3;
#pragma unroll
        for (int t4 = 0; t4 < 4; t4++) {
            uint32_t bh[4];
            ldsm4(bh, Bh + bO[cc] + (uint32_t)t4*2048);
#pragma unroll
            for (int j = 0; j < 2; j++) {
                const int nt = t4*2 + j;
                mma16816(acc2[nt], aH, bh[j*2], bh[j*2 + 1]);
                mma16816(acc2[nt], aL, bh[j*2], bh[j*2 + 1]);
            }
        }
    }

    // ---- Epilogue: unnormalized partials ----
    float* oB = (mode ? g_oW : g_oH) + ((size_t)(b*Hn + p)*Wn)*Cn;
#pragma unroll
    for (int half2 = 0; half2 < 2; half2++) {
        const int row = m0 + (lane >> 2) + half2*8;
#pragma unroll
        for (int nt = 0; nt < 8; nt++) {
            const int c = nt*8 + (lane & 3)*2;
            *(float2*)&oB[(size_t)row*Cn + c] =
                make_float2(acc2[nt][half2*2 + 0], acc2[nt][half2*2 + 1]);
        }
    }
}

// ---------------------------------------------------------------------------
// Combine (m, s) halves -> per-pixel (alphaH, alphaW)
// ---------------------------------------------------------------------------
__global__ __launch_bounds__(256) void combine_ms_k()
{
    int i = blockIdx.x*256 + threadIdx.x;
    float2 a = g_msH[i], c = g_msW[i];
    float m = fmaxf(a.x, c.x);
    float eH = __expf(a.x - m), eW = __expf(c.x - m);
    float inv = 1.0f / (a.y*eH + c.y*eW);
    g_al[i] = make_float2(eH*inv, eW*inv);
}

// ---------------------------------------------------------------------------
// Final: out[b][c][h][w] = gamma*(oHp*aH + oWp*aW) + x
// ---------------------------------------------------------------------------
__global__ __launch_bounds__(256) void final_k(const float* __restrict__ x,
                                               const float* __restrict__ gamma,
                                               float* __restrict__ out)
{
    __shared__ float s[Cn][33];
    __shared__ float2 al[32];
    const int w0 = blockIdx.x*32, h = blockIdx.y, b = blockIdx.z;
    const float g = gamma[0];
    if (threadIdx.x < 32)
        al[threadIdx.x] = g_al[(b*Hn + h)*Wn + w0 + threadIdx.x];
    __syncthreads();
    for (int i = threadIdx.x; i < 32*Cn; i += 256) {
        int wl = i >> 6, c = i & 63;
        float a = g_oH[(((size_t)b*Wn + (w0+wl))*Hn + h)*Cn + c];
        float d = g_oW[(((size_t)b*Hn + h)*Wn + (w0+wl))*Cn + c];
        float2 av = al[wl];
        s[c][wl] = g*(a*av.x + d*av.y);
    }
    __syncthreads();
    for (int i = threadIdx.x; i < Cn*32; i += 256) {
        int c = i >> 5, wl = i & 31;
        size_t idx = (((size_t)b*Cn + c)*Hn + h)*Wn + w0 + wl;
        out[idx] = s[c][wl] + x[idx];
    }
}

// ---------------------------------------------------------------------------
extern "C" void kernel_launch(void* const* d_in, const int* in_sizes, int n_in,
                              void* d_out, int out_size)
{
    (void)in_sizes; (void)n_in; (void)out_size;
    const float* x     = (const float*)d_in[0];
    const float* Wq    = (const float*)d_in[1];
    const float* bq    = (const float*)d_in[2];
    const float* Wk    = (const float*)d_in[3];
    const float* bk    = (const float*)d_in[4];
    const float* Wv    = (const float*)d_in[5];
    const float* bv    = (const float*)d_in[6];
    const float* gamma = (const float*)d_in[7];
    float* out = (float*)d_out;

    static bool attr_set = false;
    if (!attr_set) {
        cudaFuncSetAttribute(conv_mma_k, cudaFuncAttributeMaxDynamicSharedMemorySize,
                             CONV_SMEM);
        cudaFuncSetAttribute(fused_attn_k, cudaFuncAttributeMaxDynamicSharedMemorySize,
                             FUSED_SMEM);
        attr_set = true;
    }

    prep_w_k<<<(3*3*3*64*64 + 255)/256, 256>>>(Wq, Wk, Wv);
    prep_x_k<<<(Bn*Hn*32*Wn)/256, 256>>>(x);

    dim3 grid_conv(16, Bn, 3);   // (htile, b, sel) — 512-thread CTAs
    conv_mma_k<<<grid_conv, 512, CONV_SMEM>>>(bq, bk, bv);

    dim3 grid_at(128, Bn, 2);    // (p, b, mode)
    fused_attn_k<<<grid_at, 256, FUSED_SMEM>>>();

    combine_ms_k<<<(Bn*Hn*Wn)/256, 256>>>();

    dim3 grid_fin(Wn/32, Hn, Bn);
    final_k<<<grid_fin, 256>>>(x, gamma, out);
}

// round 14
// speedup vs baseline: 1.6121x; 1.0748x over previous
#include <cuda_runtime.h>
#include <cuda_fp16.h>
#include <math_constants.h>
#include <cstdint>

#define Bn 8
#define Cn 64
#define Hn 128
#define Wn 128

// ---------------------------------------------------------------------------
// Global scratch (no allocation allowed)
// q: fp16 hi+lo packed pairs; k,v: fp16 hi only. x: fp16 hi/lo.
// ---------------------------------------------------------------------------
__device__ uint32_t g_qh[Bn*Hn*Wn*32], g_ql[Bn*Hn*Wn*32];
__device__ uint32_t g_kh[Bn*Hn*Wn*32];
__device__ uint32_t g_vh[Bn*Hn*Wn*32];
__device__ uint32_t g_xh[Bn*Hn*32*Wn], g_xl[Bn*Hn*32*Wn];
__device__ float g_oH[Bn*Hn*Wn*Cn];         // [b][w][h][c]  (unnormalized)
__device__ float g_oW[Bn*Hn*Wn*Cn];         // [b][h][w][c]  (unnormalized)
__device__ float2 g_msH[Bn*Hn*Wn];
__device__ float2 g_msW[Bn*Hn*Wn];
__device__ float2 g_al[Bn*Hn*Wn];
__device__ __align__(16) char g_wf16[3*3*3*8192];

// ---------------------------------------------------------------------------
// helpers
// ---------------------------------------------------------------------------
__device__ __forceinline__ uint32_t smem_u32(const void* p) {
    uint32_t a;
    asm("{ .reg .u64 t; cvta.to.shared.u64 t, %1; cvt.u32.u64 %0, t; }"
        : "=r"(a) : "l"(p));
    return a;
}
__device__ __forceinline__ void ldsm4(uint32_t* r, uint32_t addr) {
    asm volatile("ldmatrix.sync.aligned.m8n8.x4.shared.b16 {%0,%1,%2,%3}, [%4];"
        : "=r"(r[0]), "=r"(r[1]), "=r"(r[2]), "=r"(r[3]) : "r"(addr));
}
__device__ __forceinline__ void mma16816(float (&d)[4], const uint32_t (&a)[4],
                                         uint32_t b0, uint32_t b1) {
    asm volatile("mma.sync.aligned.m16n8k16.row.col.f32.f16.f16.f32 "
        "{%0,%1,%2,%3}, {%4,%5,%6,%7}, {%8,%9}, {%0,%1,%2,%3};"
        : "+f"(d[0]), "+f"(d[1]), "+f"(d[2]), "+f"(d[3])
        : "r"(a[0]), "r"(a[1]), "r"(a[2]), "r"(a[3]), "r"(b0), "r"(b1));
}
__device__ __forceinline__ void split_pack(float a, float b,
                                           uint32_t& hp, uint32_t& lp) {
    __half ha = __float2half_rn(a), hb = __float2half_rn(b);
    __half la = __float2half_rn(a - __half2float(ha));
    __half lb = __float2half_rn(b - __half2float(hb));
    hp = ((uint32_t)__half_as_ushort(hb) << 16) | __half_as_ushort(ha);
    lp = ((uint32_t)__half_as_ushort(lb) << 16) | __half_as_ushort(la);
}

// ---------------------------------------------------------------------------
// Weight prep: OIHW fp32 -> fp16 full-co tiles, 128B rows swizzled
// ---------------------------------------------------------------------------
__global__ void prep_w_k(const float* __restrict__ Wq,
                         const float* __restrict__ Wk,
                         const float* __restrict__ Wv)
{
    int i = blockIdx.x*blockDim.x + threadIdx.x;
    if (i >= 3*3*3*64*64) return;
    int ci = i & 63; int t = i >> 6;
    int co = t & 63; t >>= 6;
    int kx = t % 3;  t /= 3;
    int ky = t % 3;  t /= 3;
    int sel = t;
    const float* Ws = (sel == 0) ? Wq : ((sel == 1) ? Wk : Wv);
    float v = Ws[((co*Cn + ci)*3 + ky)*3 + kx];
    size_t tbase = (size_t)(((sel*3 + ky)*3 + kx))*8192;
    uint32_t off = (uint32_t)co*128 + (((uint32_t)ci*2) ^ (((uint32_t)co & 7) << 4));
    *(__half*)(g_wf16 + tbase + off) = __float2half_rn(v);
}

// ---------------------------------------------------------------------------
// x pre-split: NCHW fp32 -> [b][h][cp][w] packed fp16 hi/lo
// ---------------------------------------------------------------------------
__global__ __launch_bounds__(256) void prep_x_k(const float* __restrict__ x)
{
    int id = blockIdx.x*256 + threadIdx.x;
    int w = id & 127, cp = (id >> 7) & 31, h = (id >> 12) & 127, b = id >> 19;
    float v0 = x[(((size_t)(b*64 + cp*2    ))*128 + h)*128 + w];
    float v1 = x[(((size_t)(b*64 + cp*2 + 1))*128 + h)*128 + w];
    uint32_t hp, lp;
    split_pack(v0, v1, hp, lp);
    g_xh[id] = hp;
    g_xl[id] = lp;
}

// ---------------------------------------------------------------------------
// Fused 3x3 conv via mma.sync fp16 (x split hi/lo, w single) — 512 threads.
// (unchanged from R13)
// ---------------------------------------------------------------------------
#define CONV_SMEM (73728 + 133120 + 256)

__global__ __launch_bounds__(512, 1) void conv_mma_k(const float* __restrict__ bq,
                                                     const float* __restrict__ bk,
                                                     const float* __restrict__ bv)
{
    extern __shared__ char sm[];
    char* SW = sm;                     // 9 x 8192
    char* SA = sm + 73728;             // 8 x 16640
    float* sbias = (float*)(sm + 73728 + 133120);
    const int tid = threadIdx.x, lane = tid & 31, wid = tid >> 5;
    const int b = blockIdx.y;
    const int sel = blockIdx.z;
    const int h0 = blockIdx.x * 8;
    const float* bias = (sel == 0) ? bq : ((sel == 1) ? bk : bv);
    uint32_t* gh = (sel == 0) ? g_qh : ((sel == 1) ? g_kh : g_vh);

    {
        const uint4* gw = (const uint4*)(g_wf16 + (size_t)sel*9*8192);
        for (int i = tid; i < 4608; i += 512)
            *(uint4*)(SW + i*16) = gw[i];
    }
    if (tid < 64) sbias[tid] = bias[tid];
    if (tid < 128) {
        int s8 = tid / 16, k = tid % 16;
        uint32_t off = s8*16640 + ((k < 8) ? 0u : 16512u) + (k & 7)*16;
        *(uint4*)(SA + off) = make_uint4(0,0,0,0);
    }

    for (int rr = -1; rr <= 1; rr++) {
        const int r = h0 + rr;
        const int s = (r + 4) & 3;
        char* hi = SA + (size_t)(s*2 + 0)*16640;
        char* lo = SA + (size_t)(s*2 + 1)*16640;
        const bool valid = ((unsigned)r < 128u);
        const uint32_t* xh = g_xh + (size_t)(b*Hn + (valid ? r : 0))*4096;
        const uint32_t* xl = g_xl + (size_t)(b*Hn + (valid ? r : 0))*4096;
#pragma unroll
        for (int j = 0; j < 8; j++) {
            int id = tid + j*512;
            int w = id & 127, cp = id >> 7;
            uint32_t hv = valid ? xh[id] : 0u;
            uint32_t lv = valid ? xl[id] : 0u;
            uint32_t row = (uint32_t)w + 1;
            uint32_t off = row*128 + (((uint32_t)cp*4) ^ ((row & 7) << 4));
            *(uint32_t*)(hi + off) = hv;
            *(uint32_t*)(lo + off) = lv;
        }
    }
    __syncthreads();

    const uint32_t SAb = smem_u32(SA);
    const uint32_t SWb = smem_u32(SW);
    const int m0 = (wid & 7) * 16;
    const int nh = wid >> 3;
    const int aRowSel = lane & 15;
    const int aColSel = (lane & 16) ? 16 : 0;
    const int bRowSel = (lane & 7) + ((lane & 16) ? 8 : 0);
    const int bColSel = (lane & 8) ? 16 : 0;

    uint32_t aAO[3][4], bO[4];
#pragma unroll
    for (int kx = 0; kx < 3; kx++) {
        const int arow = m0 + kx + aRowSel;
        const uint32_t axor = ((uint32_t)arow & 7) << 4;
#pragma unroll
        for (int cc = 0; cc < 4; cc++)
            aAO[kx][cc] = (uint32_t)arow*128 + (((uint32_t)(cc*32 + aColSel)) ^ axor);
    }
    {
        const int brow = nh*32 + bRowSel;
        const uint32_t bxor = ((uint32_t)brow & 7) << 4;
#pragma unroll
        for (int cc = 0; cc < 4; cc++)
            bO[cc] = (uint32_t)brow*128 + (((uint32_t)(cc*32 + bColSel)) ^ bxor);
    }

    for (int hh = 0; hh < 8; hh++) {
        const int h = h0 + hh;

        uint32_t ph[8], pl[8];
        const bool pf = (hh < 7);
        if (pf) {
            const int rn = h + 2;
            const bool valid = rn < 128;
            const uint32_t* xh = g_xh + (size_t)(b*Hn + (valid ? rn : 0))*4096;
            const uint32_t* xl = g_xl + (size_t)(b*Hn + (valid ? rn : 0))*4096;
#pragma unroll
            for (int j = 0; j < 8; j++) {
                int id = tid + j*512;
                ph[j] = valid ? xh[id] : 0u;
                pl[j] = valid ? xl[id] : 0u;
            }
        }

        float acc[4][4];
#pragma unroll
        for (int i = 0; i < 4; i++)
#pragma unroll
            for (int j = 0; j < 4; j++) acc[i][j] = 0.f;

#pragma unroll
        for (int ky = 0; ky < 3; ky++) {
            const int r = h + ky - 1;
            const int s = (r + 4) & 3;
            const uint32_t Ahi = SAb + (uint32_t)(s*2)*16640;
            const uint32_t Alo = Ahi + 16640;
#pragma unroll
            for (int kx = 0; kx < 3; kx++) {
                const uint32_t Wt = SWb + (uint32_t)((ky*3 + kx))*8192;
#pragma unroll
                for (int cc = 0; cc < 4; cc++) {
                    uint32_t ah[4], al[4], bh[8];
                    ldsm4(ah, Ahi + aAO[kx][cc]);
                    ldsm4(al, Alo + aAO[kx][cc]);
                    ldsm4(bh + 0, Wt + bO[cc]);
                    ldsm4(bh + 4, Wt + bO[cc] + 2048);
#pragma unroll
                    for (int nt = 0; nt < 4; nt++) {
                        mma16816(acc[nt], ah, bh[nt*2], bh[nt*2 + 1]);
                        mma16816(acc[nt], al, bh[nt*2], bh[nt*2 + 1]);
                    }
                }
            }
        }

        if (pf) {
            const int s = (h + 2 + 4) & 3;
            char* hi = SA + (size_t)(s*2 + 0)*16640;
            char* lo = SA + (size_t)(s*2 + 1)*16640;
#pragma unroll
            for (int j = 0; j < 8; j++) {
                int id = tid + j*512;
                int w = id & 127, cp = id >> 7;
                uint32_t row = (uint32_t)w + 1;
                uint32_t off = row*128 + (((uint32_t)cp*4) ^ ((row & 7) << 4));
                *(uint32_t*)(hi + off) = ph[j];
                *(uint32_t*)(lo + off) = pl[j];
            }
        }

        const int wr = m0 + (lane >> 2);
        const int cb = (lane & 3) * 2;
        const size_t rowBase = (size_t)(b*Hn + h)*Wn;
#pragma unroll
        for (int nt = 0; nt < 4; nt++) {
            const int c = nh*32 + nt*8 + cb;
            const float b0 = sbias[c], b1 = sbias[c + 1];
            uint32_t hp, lp;
            split_pack(acc[nt][0] + b0, acc[nt][1] + b1, hp, lp);
            gh[(rowBase + wr)*32 + (c >> 1)] = hp;
            if (sel == 0) g_ql[(rowBase + wr)*32 + (c >> 1)] = lp;
            split_pack(acc[nt][2] + b0, acc[nt][3] + b1, hp, lp);
            gh[(rowBase + wr + 8)*32 + (c >> 1)] = hp;
            if (sel == 0) g_ql[(rowBase + wr + 8)*32 + (c >> 1)] = lp;
        }
        __syncthreads();
    }
}

// ---------------------------------------------------------------------------
// FUSED attention, fp16, M-split: 128-thread CTAs (4 warps x 16 rows = 64 q-rows),
// 4 CTAs/SM. grid.x = 256 (p = x & 127, msplit = x >> 7), blockIdx.z = mode.
// ---------------------------------------------------------------------------
#define FUSED_SMEM (2*8192 + 16384 + 2*8192)

__global__ __launch_bounds__(128, 4) void fused_attn_k()
{
    extern __shared__ char sm[];
    char* QH = sm;             // 64 rows x 128B = 8KB
    char* QL = sm + 8192;      // 8KB
    char* KH = sm + 16384;     // 128 rows = 16KB
    char* VTH0 = sm + 32768;   // 8KB
    char* VTH1 = sm + 40960;   // 8KB
    const int tid = threadIdx.x, lane = tid & 31, wid = tid >> 5;
    const int p = blockIdx.x & 127, msp = blockIdx.x >> 7;
    const int b = blockIdx.y, mode = blockIdx.z;
    const int row0 = msp * 64;

    const size_t base32 = mode ? (size_t)((b*Hn + p)*Wn)*32
                               : (size_t)(b*Hn*Wn + p)*32;
    const int str32 = mode ? 32 : Wn*32;

    // Stage Q hi/lo (rows row0..row0+63)
    for (int i = tid; i < 2048; i += 128) {
        int cp = i & 31, r = i >> 5;
        uint32_t off = (uint32_t)r*128 + (((uint32_t)cp*4) ^ (((uint32_t)r & 7) << 4));
        *(uint32_t*)(QH + off) = g_qh[base32 + (size_t)(row0 + r)*str32 + cp];
        *(uint32_t*)(QL + off) = g_ql[base32 + (size_t)(row0 + r)*str32 + cp];
    }
    // Stage K hi (all 128 rows)
    for (int i = tid; i < 4096; i += 128) {
        int cp = i & 31, r = i >> 5;
        uint32_t off = (uint32_t)r*128 + (((uint32_t)cp*4) ^ (((uint32_t)r & 7) << 4));
        *(uint32_t*)(KH + off) = g_kh[base32 + (size_t)r*str32 + cp];
    }
    // Stage V transposed hi: VT[c][g]
    for (int i = tid; i < 4096; i += 128) {
        int cp = i & 31, g = i >> 5;
        uint32_t hv = g_vh[base32 + (size_t)g*str32 + cp];
        int t = g >> 6, gin = g & 63;
        int c0 = cp*2, c1 = cp*2 + 1;
        uint32_t off0 = (uint32_t)c0*128 + (((uint32_t)gin*2) ^ (((uint32_t)c0 & 7) << 4));
        uint32_t off1 = (uint32_t)c1*128 + (((uint32_t)gin*2) ^ (((uint32_t)c1 & 7) << 4));
        *(uint16_t*)((t ? VTH1 : VTH0) + off0) = (uint16_t)(hv & 0xFFFF);
        *(uint16_t*)((t ? VTH1 : VTH0) + off1) = (uint16_t)(hv >> 16);
    }
    __syncthreads();

    const uint32_t QHb = smem_u32(QH), QLb = smem_u32(QL);
    const uint32_t KHb = smem_u32(KH);
    const uint32_t VTH0b = smem_u32(VTH0), VTH1b = smem_u32(VTH1);
    const int m0 = wid * 16;                 // local row tile (0..48)
    const int aRowSel = lane & 15;
    const int aColSel = (lane & 16) ? 16 : 0;
    const int bRowSel = (lane & 7) + ((lane & 16) ? 8 : 0);
    const int bColSel = (lane & 8) ? 16 : 0;

    uint32_t aO[4], bO[4];
    {
        const int arow = m0 + aRowSel;
        const uint32_t axor = ((uint32_t)arow & 7) << 4;
        const uint32_t bxor = ((uint32_t)bRowSel & 7) << 4;
#pragma unroll
        for (int kc = 0; kc < 4; kc++) {
            aO[kc] = (uint32_t)arow*128 + (((uint32_t)(kc*32 + aColSel)) ^ axor);
            bO[kc] = (uint32_t)bRowSel*128 + (((uint32_t)(kc*32 + bColSel)) ^ bxor);
        }
    }

    // ---- Phase 1: logits (64 local rows x 128 g) ----
    float acc[16][4];
#pragma unroll
    for (int i = 0; i < 16; i++)
#pragma unroll
        for (int j = 0; j < 4; j++) acc[i][j] = 0.f;

#pragma unroll
    for (int kc = 0; kc < 4; kc++) {
        uint32_t ah[4], al[4];
        ldsm4(ah, QHb + aO[kc]);
        ldsm4(al, QLb + aO[kc]);
#pragma unroll
        for (int t8 = 0; t8 < 8; t8++) {
            uint32_t bh[4];
            ldsm4(bh, KHb + bO[kc] + (uint32_t)t8*2048);
#pragma unroll
            for (int j = 0; j < 2; j++) {
                const int a = t8*2 + j;
                mma16816(acc[a], ah, bh[j*2], bh[j*2 + 1]);
                mma16816(acc[a], al, bh[j*2], bh[j*2 + 1]);
            }
        }
    }

    // ---- Phase 2: mask + local softmax + e = exp(l - m) in place ----
    const int msBase = mode ? (b*Hn + p)*Wn : b*Hn*Wn + p;
    const int msStr  = mode ? 1 : Wn;
    float2* msOut = mode ? g_msW : g_msH;

#pragma unroll
    for (int half2 = 0; half2 < 2; half2++) {
        const int grow = row0 + m0 + (lane >> 2) + half2*8;
        if (!mode) {
#pragma unroll
            for (int nt = 0; nt < 16; nt++) {
                const int g = nt*8 + (lane & 3)*2;
                if (grow == g)     acc[nt][half2*2 + 0] = -CUDART_INF_F;
                if (grow == g + 1) acc[nt][half2*2 + 1] = -CUDART_INF_F;
            }
        }
        float m = acc[0][half2*2];
#pragma unroll
        for (int nt = 0; nt < 16; nt++) {
            m = fmaxf(m, acc[nt][half2*2 + 0]);
            m = fmaxf(m, acc[nt][half2*2 + 1]);
        }
        m = fmaxf(m, __shfl_xor_sync(~0u, m, 1));
        m = fmaxf(m, __shfl_xor_sync(~0u, m, 2));
        float s = 0.f;
#pragma unroll
        for (int nt = 0; nt < 16; nt++) {
            float e0 = __expf(acc[nt][half2*2 + 0] - m);
            float e1 = __expf(acc[nt][half2*2 + 1] - m);
            acc[nt][half2*2 + 0] = e0;
            acc[nt][half2*2 + 1] = e1;
            s += e0 + e1;
        }
        s += __shfl_xor_sync(~0u, s, 1);
        s += __shfl_xor_sync(~0u, s, 2);
        if ((lane & 3) == 0) msOut[msBase + grow*msStr] = make_float2(m, s);
    }

    // ---- Pack P fragments (fp16 hi/lo) in place ----
    uint32_t ap[64];
#pragma unroll
    for (int kc = 0; kc < 8; kc++) {
        split_pack(acc[2*kc    ][0], acc[2*kc    ][1], ap[kc*8 + 0], ap[kc*8 + 4]);
        split_pack(acc[2*kc    ][2], acc[2*kc    ][3], ap[kc*8 + 1], ap[kc*8 + 5]);
        split_pack(acc[2*kc + 1][0], acc[2*kc + 1][1], ap[kc*8 + 2], ap[kc*8 + 6]);
        split_pack(acc[2*kc + 1][2], acc[2*kc + 1][3], ap[kc*8 + 3], ap[kc*8 + 7]);
    }

    // ---- Phase 3: out partial = P * V ----
    float acc2[8][4];
#pragma unroll
    for (int i = 0; i < 8; i++)
#pragma unroll
        for (int j = 0; j < 4; j++) acc2[i][j] = 0.f;

#pragma unroll
    for (int kc = 0; kc < 8; kc++) {
        const uint32_t (&aH)[4] = *reinterpret_cast<const uint32_t(*)[4]>(ap + kc*8);
        const uint32_t (&aL)[4] = *reinterpret_cast<const uint32_t(*)[4]>(ap + kc*8 + 4);
        const uint32_t Bh = (kc < 4) ? VTH0b : VTH1b;
        const int cc = kc & 3;
#pragma unroll
        for (int t4 = 0; t4 < 4; t4++) {
            uint32_t bh[4];
            ldsm4(bh, Bh + bO[cc] + (uint32_t)t4*2048);
#pragma unroll
            for (int j = 0; j < 2; j++) {
                const int nt = t4*2 + j;
                mma16816(acc2[nt], aH, bh[j*2], bh[j*2 + 1]);
                mma16816(acc2[nt], aL, bh[j*2], bh[j*2 + 1]);
            }
        }
    }

    // ---- Epilogue: unnormalized partials ----
    float* oB = (mode ? g_oW : g_oH) + ((size_t)(b*Hn + p)*Wn)*Cn;
#pragma unroll
    for (int half2 = 0; half2 < 2; half2++) {
        const int grow = row0 + m0 + (lane >> 2) + half2*8;
#pragma unroll
        for (int nt = 0; nt < 8; nt++) {
            const int c = nt*8 + (lane & 3)*2;
            *(float2*)&oB[(size_t)grow*Cn + c] =
                make_float2(acc2[nt][half2*2 + 0], acc2[nt][half2*2 + 1]);
        }
    }
}

// ---------------------------------------------------------------------------
// Combine (m, s) halves -> per-pixel (alphaH, alphaW)
// ---------------------------------------------------------------------------
__global__ __launch_bounds__(256) void combine_ms_k()
{
    int i = blockIdx.x*256 + threadIdx.x;
    float2 a = g_msH[i], c = g_msW[i];
    float m = fmaxf(a.x, c.x);
    float eH = __expf(a.x - m), eW = __expf(c.x - m);
    float inv = 1.0f / (a.y*eH + c.y*eW);
    g_al[i] = make_float2(eH*inv, eW*inv);
}

// ---------------------------------------------------------------------------
// Final: out[b][c][h][w] = gamma*(oHp*aH + oWp*aW) + x
// ---------------------------------------------------------------------------
__global__ __launch_bounds__(256) void final_k(const float* __restrict__ x,
                                               const float* __restrict__ gamma,
                                               float* __restrict__ out)
{
    __shared__ float s[Cn][33];
    __shared__ float2 al[32];
    const int w0 = blockIdx.x*32, h = blockIdx.y, b = blockIdx.z;
    const float g = gamma[0];
    if (threadIdx.x < 32)
        al[threadIdx.x] = g_al[(b*Hn + h)*Wn + w0 + threadIdx.x];
    __syncthreads();
    for (int i = threadIdx.x; i < 32*Cn; i += 256) {
        int wl = i >> 6, c = i & 63;
        float a = g_oH[(((size_t)b*Wn + (w0+wl))*Hn + h)*Cn + c];
        float d = g_oW[(((size_t)b*Hn + h)*Wn + (w0+wl))*Cn + c];
        float2 av = al[wl];
        s[c][wl] = g*(a*av.x + d*av.y);
    }
    __syncthreads();
    for (int i = threadIdx.x; i < Cn*32; i += 256) {
        int c = i >> 5, wl = i & 31;
        size_t idx = (((size_t)b*Cn + c)*Hn + h)*Wn + w0 + wl;
        out[idx] = s[c][wl] + x[idx];
    }
}

// ---------------------------------------------------------------------------
extern "C" void kernel_launch(void* const* d_in, const int* in_sizes, int n_in,
                              void* d_out, int out_size)
{
    (void)in_sizes; (void)n_in; (void)out_size;
    const float* x     = (const float*)d_in[0];
    const float* Wq    = (const float*)d_in[1];
    const float* bq    = (const float*)d_in[2];
    const float* Wk    = (const float*)d_in[3];
    const float* bk    = (const float*)d_in[4];
    const float* Wv    = (const float*)d_in[5];
    const float* bv    = (const float*)d_in[6];
    const float* gamma = (const float*)d_in[7];
    float* out = (float*)d_out;

    static bool attr_set = false;
    if (!attr_set) {
        cudaFuncSetAttribute(conv_mma_k, cudaFuncAttributeMaxDynamicSharedMemorySize,
                             CONV_SMEM);
        cudaFuncSetAttribute(fused_attn_k, cudaFuncAttributeMaxDynamicSharedMemorySize,
                             FUSED_SMEM);
        attr_set = true;
    }

    prep_w_k<<<(3*3*3*64*64 + 255)/256, 256>>>(Wq, Wk, Wv);
    prep_x_k<<<(Bn*Hn*32*Wn)/256, 256>>>(x);

    dim3 grid_conv(16, Bn, 3);   // (htile, b, sel)
    conv_mma_k<<<grid_conv, 512, CONV_SMEM>>>(bq, bk, bv);

    dim3 grid_at(256, Bn, 2);    // (msplit*128 + p, b, mode)
    fused_attn_k<<<grid_at, 128, FUSED_SMEM>>>();

    combine_ms_k<<<(Bn*Hn*Wn)/256, 256>>>();

    dim3 grid_fin(Wn/32, Hn, Bn);
    final_k<<<grid_fin, 256>>>(x, gamma, out);
}

// round 17
// speedup vs baseline: 1.9645x; 1.2186x over previous
#include <cuda_runtime.h>
#include <cuda_fp16.h>
#include <math_constants.h>
#include <cstdint>

#define Bn 8
#define Cn 64
#define Hn 128
#define Wn 128

// ---------------------------------------------------------------------------
// Global scratch (no allocation allowed)
// ---------------------------------------------------------------------------
__device__ uint32_t g_qh[Bn*Hn*Wn*32], g_ql[Bn*Hn*Wn*32];
__device__ uint32_t g_kh[Bn*Hn*Wn*32];
__device__ uint32_t g_vh[Bn*Hn*Wn*32];
__device__ uint32_t g_xh[Bn*Hn*32*Wn], g_xl[Bn*Hn*32*Wn];
__device__ float g_oH[Bn*Hn*Wn*Cn];         // [b][w][h][c]  (unnormalized)
__device__ float g_oW[Bn*Hn*Wn*Cn];         // [b][h][w][c]  (unnormalized)
__device__ float2 g_msH[Bn*Hn*Wn];          // pixel-major [b][h][w]
__device__ float2 g_msW[Bn*Hn*Wn];
__device__ __align__(16) char g_wf16[3*3*3*8192];

// ---------------------------------------------------------------------------
// helpers
// ---------------------------------------------------------------------------
__device__ __forceinline__ uint32_t smem_u32(const void* p) {
    uint32_t a;
    asm("{ .reg .u64 t; cvta.to.shared.u64 t, %1; cvt.u32.u64 %0, t; }"
        : "=r"(a) : "l"(p));
    return a;
}
__device__ __forceinline__ void ldsm4(uint32_t* r, uint32_t addr) {
    asm volatile("ldmatrix.sync.aligned.m8n8.x4.shared.b16 {%0,%1,%2,%3}, [%4];"
        : "=r"(r[0]), "=r"(r[1]), "=r"(r[2]), "=r"(r[3]) : "r"(addr));
}
__device__ __forceinline__ void ldsm4t(uint32_t* r, uint32_t addr) {
    asm volatile("ldmatrix.sync.aligned.m8n8.x4.trans.shared.b16 {%0,%1,%2,%3}, [%4];"
        : "=r"(r[0]), "=r"(r[1]), "=r"(r[2]), "=r"(r[3]) : "r"(addr));
}
__device__ __forceinline__ void mma16816(float (&d)[4], const uint32_t (&a)[4],
                                         uint32_t b0, uint32_t b1) {
    asm volatile("mma.sync.aligned.m16n8k16.row.col.f32.f16.f16.f32 "
        "{%0,%1,%2,%3}, {%4,%5,%6,%7}, {%8,%9}, {%0,%1,%2,%3};"
        : "+f"(d[0]), "+f"(d[1]), "+f"(d[2]), "+f"(d[3])
        : "r"(a[0]), "r"(a[1]), "r"(a[2]), "r"(a[3]), "r"(b0), "r"(b1));
}
__device__ __forceinline__ void split_pack(float a, float b,
                                           uint32_t& hp, uint32_t& lp) {
    __half ha = __float2half_rn(a), hb = __float2half_rn(b);
    __half la = __float2half_rn(a - __half2float(ha));
    __half lb = __float2half_rn(b - __half2float(hb));
    hp = ((uint32_t)__half_as_ushort(hb) << 16) | __half_as_ushort(ha);
    lp = ((uint32_t)__half_as_ushort(lb) << 16) | __half_as_ushort(la);
}

// ---------------------------------------------------------------------------
// Weight prep
// ---------------------------------------------------------------------------
__global__ void prep_w_k(const float* __restrict__ Wq,
                         const float* __restrict__ Wk,
                         const float* __restrict__ Wv)
{
    int i = blockIdx.x*blockDim.x + threadIdx.x;
    if (i >= 3*3*3*64*64) return;
    int ci = i & 63; int t = i >> 6;
    int co = t & 63; t >>= 6;
    int kx = t % 3;  t /= 3;
    int ky = t % 3;  t /= 3;
    int sel = t;
    const float* Ws = (sel == 0) ? Wq : ((sel == 1) ? Wk : Wv);
    float v = Ws[((co*Cn + ci)*3 + ky)*3 + kx];
    size_t tbase = (size_t)(((sel*3 + ky)*3 + kx))*8192;
    uint32_t off = (uint32_t)co*128 + (((uint32_t)ci*2) ^ (((uint32_t)co & 7) << 4));
    *(__half*)(g_wf16 + tbase + off) = __float2half_rn(v);
}

// ---------------------------------------------------------------------------
// x pre-split: NCHW fp32 -> [b][h][cp][w] packed fp16 hi/lo
// ---------------------------------------------------------------------------
__global__ __launch_bounds__(256) void prep_x_k(const float* __restrict__ x)
{
    int id = blockIdx.x*256 + threadIdx.x;
    int w = id & 127, cp = (id >> 7) & 31, h = (id >> 12) & 127, b = id >> 19;
    float v0 = x[(((size_t)(b*64 + cp*2    ))*128 + h)*128 + w];
    float v1 = x[(((size_t)(b*64 + cp*2 + 1))*128 + h)*128 + w];
    uint32_t hp, lp;
    split_pack(v0, v1, hp, lp);
    g_xh[id] = hp;
    g_xl[id] = lp;
}

// ---------------------------------------------------------------------------
// Fused 3x3 conv via mma.sync fp16 — 512 threads (unchanged from R13/R14)
// ---------------------------------------------------------------------------
#define CONV_SMEM (73728 + 133120 + 256)

__global__ __launch_bounds__(512, 1) void conv_mma_k(const float* __restrict__ bq,
                                                     const float* __restrict__ bk,
                                                     const float* __restrict__ bv)
{
    extern __shared__ char sm[];
    char* SW = sm;                     // 9 x 8192
    char* SA = sm + 73728;             // 8 x 16640
    float* sbias = (float*)(sm + 73728 + 133120);
    const int tid = threadIdx.x, lane = tid & 31, wid = tid >> 5;
    const int b = blockIdx.y;
    const int sel = blockIdx.z;
    const int h0 = blockIdx.x * 8;
    const float* bias = (sel == 0) ? bq : ((sel == 1) ? bk : bv);
    uint32_t* gh = (sel == 0) ? g_qh : ((sel == 1) ? g_kh : g_vh);

    {
        const uint4* gw = (const uint4*)(g_wf16 + (size_t)sel*9*8192);
        for (int i = tid; i < 4608; i += 512)
            *(uint4*)(SW + i*16) = gw[i];
    }
    if (tid < 64) sbias[tid] = bias[tid];
    if (tid < 128) {
        int s8 = tid / 16, k = tid % 16;
        uint32_t off = s8*16640 + ((k < 8) ? 0u : 16512u) + (k & 7)*16;
        *(uint4*)(SA + off) = make_uint4(0,0,0,0);
    }

    for (int rr = -1; rr <= 1; rr++) {
        const int r = h0 + rr;
        const int s = (r + 4) & 3;
        char* hi = SA + (size_t)(s*2 + 0)*16640;
        char* lo = SA + (size_t)(s*2 + 1)*16640;
        const bool valid = ((unsigned)r < 128u);
        const uint32_t* xh = g_xh + (size_t)(b*Hn + (valid ? r : 0))*4096;
        const uint32_t* xl = g_xl + (size_t)(b*Hn + (valid ? r : 0))*4096;
#pragma unroll
        for (int j = 0; j < 8; j++) {
            int id = tid + j*512;
            int w = id & 127, cp = id >> 7;
            uint32_t hv = valid ? xh[id] : 0u;
            uint32_t lv = valid ? xl[id] : 0u;
            uint32_t row = (uint32_t)w + 1;
            uint32_t off = row*128 + (((uint32_t)cp*4) ^ ((row & 7) << 4));
            *(uint32_t*)(hi + off) = hv;
            *(uint32_t*)(lo + off) = lv;
        }
    }
    __syncthreads();

    const uint32_t SAb = smem_u32(SA);
    const uint32_t SWb = smem_u32(SW);
    const int m0 = (wid & 7) * 16;
    const int nh = wid >> 3;
    const int aRowSel = lane & 15;
    const int aColSel = (lane & 16) ? 16 : 0;
    const int bRowSel = (lane & 7) + ((lane & 16) ? 8 : 0);
    const int bColSel = (lane & 8) ? 16 : 0;

    uint32_t aAO[3][4], bO[4];
#pragma unroll
    for (int kx = 0; kx < 3; kx++) {
        const int arow = m0 + kx + aRowSel;
        const uint32_t axor = ((uint32_t)arow & 7) << 4;
#pragma unroll
        for (int cc = 0; cc < 4; cc++)
            aAO[kx][cc] = (uint32_t)arow*128 + (((uint32_t)(cc*32 + aColSel)) ^ axor);
    }
    {
        const int brow = nh*32 + bRowSel;
        const uint32_t bxor = ((uint32_t)brow & 7) << 4;
#pragma unroll
        for (int cc = 0; cc < 4; cc++)
            bO[cc] = (uint32_t)brow*128 + (((uint32_t)(cc*32 + bColSel)) ^ bxor);
    }

    for (int hh = 0; hh < 8; hh++) {
        const int h = h0 + hh;

        uint32_t ph[8], pl[8];
        const bool pf = (hh < 7);
        if (pf) {
            const int rn = h + 2;
            const bool valid = rn < 128;
            const uint32_t* xh = g_xh + (size_t)(b*Hn + (valid ? rn : 0))*4096;
            const uint32_t* xl = g_xl + (size_t)(b*Hn + (valid ? rn : 0))*4096;
#pragma unroll
            for (int j = 0; j < 8; j++) {
                int id = tid + j*512;
                ph[j] = valid ? xh[id] : 0u;
                pl[j] = valid ? xl[id] : 0u;
            }
        }

        float acc[4][4];
#pragma unroll
        for (int i = 0; i < 4; i++)
#pragma unroll
            for (int j = 0; j < 4; j++) acc[i][j] = 0.f;

#pragma unroll
        for (int ky = 0; ky < 3; ky++) {
            const int r = h + ky - 1;
            const int s = (r + 4) & 3;
            const uint32_t Ahi = SAb + (uint32_t)(s*2)*16640;
            const uint32_t Alo = Ahi + 16640;
#pragma unroll
            for (int kx = 0; kx < 3; kx++) {
                const uint32_t Wt = SWb + (uint32_t)((ky*3 + kx))*8192;
#pragma unroll
                for (int cc = 0; cc < 4; cc++) {
                    uint32_t ah[4], al[4], bh[8];
                    ldsm4(ah, Ahi + aAO[kx][cc]);
                    ldsm4(al, Alo + aAO[kx][cc]);
                    ldsm4(bh + 0, Wt + bO[cc]);
                    ldsm4(bh + 4, Wt + bO[cc] + 2048);
#pragma unroll
                    for (int nt = 0; nt < 4; nt++) {
                        mma16816(acc[nt], ah, bh[nt*2], bh[nt*2 + 1]);
                        mma16816(acc[nt], al, bh[nt*2], bh[nt*2 + 1]);
                    }
                }
            }
        }

        if (pf) {
            const int s = (h + 2 + 4) & 3;
            char* hi = SA + (size_t)(s*2 + 0)*16640;
            char* lo = SA + (size_t)(s*2 + 1)*16640;
#pragma unroll
            for (int j = 0; j < 8; j++) {
                int id = tid + j*512;
                int w = id & 127, cp = id >> 7;
                uint32_t row = (uint32_t)w + 1;
                uint32_t off = row*128 + (((uint32_t)cp*4) ^ ((row & 7) << 4));
                *(uint32_t*)(hi + off) = ph[j];
                *(uint32_t*)(lo + off) = pl[j];
            }
        }

        const int wr = m0 + (lane >> 2);
        const int cb = (lane & 3) * 2;
        const size_t rowBase = (size_t)(b*Hn + h)*Wn;
#pragma unroll
        for (int nt = 0; nt < 4; nt++) {
            const int c = nh*32 + nt*8 + cb;
            const float b0 = sbias[c], b1 = sbias[c + 1];
            uint32_t hp, lp;
            split_pack(acc[nt][0] + b0, acc[nt][1] + b1, hp, lp);
            gh[(rowBase + wr)*32 + (c >> 1)] = hp;
            if (sel == 0) g_ql[(rowBase + wr)*32 + (c >> 1)] = lp;
            split_pack(acc[nt][2] + b0, acc[nt][3] + b1, hp, lp);
            gh[(rowBase + wr + 8)*32 + (c >> 1)] = hp;
            if (sel == 0) g_ql[(rowBase + wr + 8)*32 + (c >> 1)] = lp;
        }
        __syncthreads();
    }
}

// ---------------------------------------------------------------------------
// FUSED attention, fp16, M-split 64 rows, uint4 staging, V via ldmatrix.trans.
// grid.x = 256 (p = x & 127, msplit = x >> 7), blockIdx.z = mode.
// ---------------------------------------------------------------------------
#define FUSED_SMEM (8192 + 8192 + 16384 + 16384)

__global__ __launch_bounds__(128, 4) void fused_attn_k()
{
    extern __shared__ char sm[];
    char* QH = sm;             // 64 rows x 128B
    char* QL = sm + 8192;
    char* KH = sm + 16384;     // 128 rows
    char* VH = sm + 32768;     // 128 rows (untransposed [g][c])
    const int tid = threadIdx.x, lane = tid & 31, wid = tid >> 5;
    const int p = blockIdx.x & 127, msp = blockIdx.x >> 7;
    const int b = blockIdx.y, mode = blockIdx.z;
    const int row0 = msp * 64;

    const size_t base32 = mode ? (size_t)((b*Hn + p)*Wn)*32
                               : (size_t)(b*Hn*Wn + p)*32;
    const int str32 = mode ? 32 : Wn*32;

    // Stage Q hi/lo (64 rows, uint4)
    for (int i = tid; i < 512; i += 128) {
        int c4 = i & 7, r = i >> 3;
        uint32_t off = (uint32_t)r*128 + (((uint32_t)c4*16) ^ (((uint32_t)r & 7) << 4));
        const size_t gidx = base32 + (size_t)(row0 + r)*str32 + c4*4;
        *(uint4*)(QH + off) = *(const uint4*)(g_qh + gidx);
        *(uint4*)(QL + off) = *(const uint4*)(g_ql + gidx);
    }
    // Stage K and V hi (128 rows each, uint4, straight rows)
    for (int i = tid; i < 1024; i += 128) {
        int c4 = i & 7, r = i >> 3;
        uint32_t off = (uint32_t)r*128 + (((uint32_t)c4*16) ^ (((uint32_t)r & 7) << 4));
        const size_t gidx = base32 + (size_t)r*str32 + c4*4;
        *(uint4*)(KH + off) = *(const uint4*)(g_kh + gidx);
        *(uint4*)(VH + off) = *(const uint4*)(g_vh + gidx);
    }
    __syncthreads();

    const uint32_t QHb = smem_u32(QH), QLb = smem_u32(QL);
    const uint32_t KHb = smem_u32(KH), VHb = smem_u32(VH);
    const int m0 = wid * 16;
    const int aRowSel = lane & 15;
    const int aColSel = (lane & 16) ? 16 : 0;
    const int bRowSel = (lane & 7) + ((lane & 16) ? 8 : 0);
    const int bColSel = (lane & 8) ? 16 : 0;
    // trans-load lane mapping (phase 3): rows within 16-k block, col by lane>=16
    const int tRowSel = (lane & 7) + ((lane & 8) ? 8 : 0);
    const int tColSel = (lane & 16) ? 16 : 0;

    uint32_t aO[4], bO[4];
    {
        const int arow = m0 + aRowSel;
        const uint32_t axor = ((uint32_t)arow & 7) << 4;
        const uint32_t bxor = ((uint32_t)bRowSel & 7) << 4;
#pragma unroll
        for (int kc = 0; kc < 4; kc++) {
            aO[kc] = (uint32_t)arow*128 + (((uint32_t)(kc*32 + aColSel)) ^ axor);
            bO[kc] = (uint32_t)bRowSel*128 + (((uint32_t)(kc*32 + bColSel)) ^ bxor);
        }
    }

    // ---- Phase 1: logits (64 local rows x 128 g) ----
    float acc[16][4];
#pragma unroll
    for (int i = 0; i < 16; i++)
#pragma unroll
        for (int j = 0; j < 4; j++) acc[i][j] = 0.f;

#pragma unroll
    for (int kc = 0; kc < 4; kc++) {
        uint32_t ah[4], al[4];
        ldsm4(ah, QHb + aO[kc]);
        ldsm4(al, QLb + aO[kc]);
#pragma unroll
        for (int t8 = 0; t8 < 8; t8++) {
            uint32_t bh[4];
            ldsm4(bh, KHb + bO[kc] + (uint32_t)t8*2048);
#pragma unroll
            for (int j = 0; j < 2; j++) {
                const int a = t8*2 + j;
                mma16816(acc[a], ah, bh[j*2], bh[j*2 + 1]);
                mma16816(acc[a], al, bh[j*2], bh[j*2 + 1]);
            }
        }
    }

    // ---- Phase 2: mask + local softmax + e = exp(l - m) in place ----
    const int msIdx0 = mode ? ((b*Hn + p)*Wn) : (b*Hn*Wn + p);
    const int msStr  = mode ? 1 : Wn;
    float2* msOut = mode ? g_msW : g_msH;

#pragma unroll
    for (int half2 = 0; half2 < 2; half2++) {
        const int grow = row0 + m0 + (lane >> 2) + half2*8;
        if (!mode) {
#pragma unroll
            for (int nt = 0; nt < 16; nt++) {
                const int g = nt*8 + (lane & 3)*2;
                if (grow == g)     acc[nt][half2*2 + 0] = -CUDART_INF_F;
                if (grow == g + 1) acc[nt][half2*2 + 1] = -CUDART_INF_F;
            }
        }
        float m = acc[0][half2*2];
#pragma unroll
        for (int nt = 0; nt < 16; nt++) {
            m = fmaxf(m, acc[nt][half2*2 + 0]);
            m = fmaxf(m, acc[nt][half2*2 + 1]);
        }
        m = fmaxf(m, __shfl_xor_sync(~0u, m, 1));
        m = fmaxf(m, __shfl_xor_sync(~0u, m, 2));
        float s = 0.f;
#pragma unroll
        for (int nt = 0; nt < 16; nt++) {
            float e0 = __expf(acc[nt][half2*2 + 0] - m);
            float e1 = __expf(acc[nt][half2*2 + 1] - m);
            acc[nt][half2*2 + 0] = e0;
            acc[nt][half2*2 + 1] = e1;
            s += e0 + e1;
        }
        s += __shfl_xor_sync(~0u, s, 1);
        s += __shfl_xor_sync(~0u, s, 2);
        if ((lane & 3) == 0) msOut[msIdx0 + grow*msStr] = make_float2(m, s);
    }

    // ---- Pack P fragments (fp16 hi/lo) in place ----
    uint32_t ap[64];
#pragma unroll
    for (int kc = 0; kc < 8; kc++) {
        split_pack(acc[2*kc    ][0], acc[2*kc    ][1], ap[kc*8 + 0], ap[kc*8 + 4]);
        split_pack(acc[2*kc    ][2], acc[2*kc    ][3], ap[kc*8 + 1], ap[kc*8 + 5]);
        split_pack(acc[2*kc + 1][0], acc[2*kc + 1][1], ap[kc*8 + 2], ap[kc*8 + 6]);
        split_pack(acc[2*kc + 1][2], acc[2*kc + 1][3], ap[kc*8 + 3], ap[kc*8 + 7]);
    }

    // ---- Phase 3: out partial = P * V, B via ldmatrix.trans on VH[g][c] ----
    float acc2[8][4];
#pragma unroll
    for (int i = 0; i < 8; i++)
#pragma unroll
        for (int j = 0; j < 4; j++) acc2[i][j] = 0.f;

    const uint32_t txor = ((uint32_t)tRowSel & 7) << 4;
#pragma unroll
    for (int kc = 0; kc < 8; kc++) {
        const uint32_t (&aH)[4] = *reinterpret_cast<const uint32_t(*)[4]>(ap + kc*8);
        const uint32_t (&aL)[4] = *reinterpret_cast<const uint32_t(*)[4]>(ap + kc*8 + 4);
        const uint32_t rowOff = (uint32_t)(kc*16 + tRowSel)*128;
#pragma unroll
        for (int t4 = 0; t4 < 4; t4++) {
            uint32_t bh[4];
            ldsm4t(bh, VHb + rowOff + (((uint32_t)(t4*32 + tColSel)) ^ txor));
#pragma unroll
            for (int j = 0; j < 2; j++) {
                const int nt = t4*2 + j;
                mma16816(acc2[nt], aH, bh[j*2], bh[j*2 + 1]);
                mma16816(acc2[nt], aL, bh[j*2], bh[j*2 + 1]);
            }
        }
    }

    // ---- Epilogue: unnormalized partials ----
    float* oB = (mode ? g_oW : g_oH) + ((size_t)(b*Hn + p)*Wn)*Cn;
#pragma unroll
    for (int half2 = 0; half2 < 2; half2++) {
        const int grow = row0 + m0 + (lane >> 2) + half2*8;
#pragma unroll
        for (int nt = 0; nt < 8; nt++) {
            const int c = nt*8 + (lane & 3)*2;
            *(float2*)&oB[(size_t)grow*Cn + c] =
                make_float2(acc2[nt][half2*2 + 0], acc2[nt][half2*2 + 1]);
        }
    }
}

// ---------------------------------------------------------------------------
// Final: alphas inline + out[b][c][h][w] = gamma*(oHp*aH + oWp*aW) + x
// ---------------------------------------------------------------------------
__global__ __launch_bounds__(256) void final_k(const float* __restrict__ x,
                                               const float* __restrict__ gamma,
                                               float* __restrict__ out)
{
    __shared__ float s[Cn][33];
    __shared__ float2 al[32];
    const int w0 = blockIdx.x*32, h = blockIdx.y, b = blockIdx.z;
    const float g = gamma[0];
    if (threadIdx.x < 32) {
        int i = (b*Hn + h)*Wn + w0 + threadIdx.x;
        float2 a = g_msH[i], c = g_msW[i];
        float m = fmaxf(a.x, c.x);
        float eH = __expf(a.x - m), eW = __expf(c.x - m);
        float inv = 1.0f / (a.y*eH + c.y*eW);
        al[threadIdx.x] = make_float2(eH*inv, eW*inv);
    }
    __syncthreads();
    for (int i = threadIdx.x; i < 32*Cn; i += 256) {
        int wl = i >> 6, c = i & 63;
        float a = g_oH[(((size_t)b*Wn + (w0+wl))*Hn + h)*Cn + c];
        float d = g_oW[(((size_t)b*Hn + h)*Wn + (w0+wl))*Cn + c];
        float2 av = al[wl];
        s[c][wl] = g*(a*av.x + d*av.y);
    }
    __syncthreads();
    for (int i = threadIdx.x; i < Cn*32; i += 256) {
        int c = i >> 5, wl = i & 31;
        size_t idx = (((size_t)b*Cn + c)*Hn + h)*Wn + w0 + wl;
        out[idx] = s[c][wl] + x[idx];
    }
}

// ---------------------------------------------------------------------------
extern "C" void kernel_launch(void* const* d_in, const int* in_sizes, int n_in,
                              void* d_out, int out_size)
{
    (void)in_sizes; (void)n_in; (void)out_size;
    const float* x     = (const float*)d_in[0];
    const float* Wq    = (const float*)d_in[1];
    const float* bq    = (const float*)d_in[2];
    const float* Wk    = (const float*)d_in[3];
    const float* bk    = (const float*)d_in[4];
    const float* Wv    = (const float*)d_in[5];
    const float* bv    = (const float*)d_in[6];
    const float* gamma = (const float*)d_in[7];
    float* out = (float*)d_out;

    static bool attr_set = false;
    if (!attr_set) {
        cudaFuncSetAttribute(conv_mma_k, cudaFuncAttributeMaxDynamicSharedMemorySize,
                             CONV_SMEM);
        cudaFuncSetAttribute(fused_attn_k, cudaFuncAttributeMaxDynamicSharedMemorySize,
                             FUSED_SMEM);
        attr_set = true;
    }

    prep_w_k<<<(3*3*3*64*64 + 255)/256, 256>>>(Wq, Wk, Wv);
    prep_x_k<<<(Bn*Hn*32*Wn)/256, 256>>>(x);

    dim3 grid_conv(16, Bn, 3);   // (htile, b, sel)
    conv_mma_k<<<grid_conv, 512, CONV_SMEM>>>(bq, bk, bv);

    dim3 grid_at(256, Bn, 2);    // (msplit*128 + p, b, mode)
    fused_attn_k<<<grid_at, 128, FUSED_SMEM>>>();

    dim3 grid_fin(Wn/32, Hn, Bn);
    final_k<<<grid_fin, 256>>>(x, gamma, out);
}